// round 3
// baseline (speedup 1.0000x reference)
#include <cuda_runtime.h>
#include <math.h>

// Problem constants
#define BB   2
#define SS   2048
#define DD   1024
#define HH   16
#define DH   64
#define MM   (BB*SS)     // 4096
#define BH   (BB*HH)     // 32

// Scratch (device globals: allocation-free)
__device__ float g_qh[(size_t)BH*SS*DH];   // [B,H,S,DH]
__device__ float g_kh[(size_t)BH*SS*DH];
__device__ float g_vh[(size_t)BH*SS*DH];
__device__ float g_ctx[(size_t)MM*DD];     // [B,S,D]

// ---------------------------------------------------------------------------
// C = A[M,K] @ W[N,K]^T  (torch Linear).  M=4096, N=K=1024.
// head_split=1: write C into [B,H,S,DH] layout (for Q/K/V projections).
// Tiles: 64x64 per CTA, k-tile 16, 256 threads, 4x4 per-thread microtile.
// ---------------------------------------------------------------------------
__global__ __launch_bounds__(256) void gemm_nt_kernel(
    const float* __restrict__ A, const float* __restrict__ W,
    float* __restrict__ C, int head_split)
{
    const int K = DD, N = DD;
    __shared__ float As[16][64];
    __shared__ float Ws[16][64];
    const int m0 = blockIdx.y * 64, n0 = blockIdx.x * 64;
    const int tid = threadIdx.x;
    const int tx = tid & 15, ty = tid >> 4;
    const int lr = tid >> 2;          // 0..63
    const int lc = (tid & 3) * 4;     // 0,4,8,12

    float acc[4][4] = {};

    for (int k0 = 0; k0 < K; k0 += 16) {
        float4 va = *(const float4*)&A[(size_t)(m0 + lr) * K + k0 + lc];
        float4 vw = *(const float4*)&W[(size_t)(n0 + lr) * K + k0 + lc];
        As[lc + 0][lr] = va.x; As[lc + 1][lr] = va.y;
        As[lc + 2][lr] = va.z; As[lc + 3][lr] = va.w;
        Ws[lc + 0][lr] = vw.x; Ws[lc + 1][lr] = vw.y;
        Ws[lc + 2][lr] = vw.z; Ws[lc + 3][lr] = vw.w;
        __syncthreads();
        #pragma unroll
        for (int kk = 0; kk < 16; kk++) {
            float4 a4 = *(const float4*)&As[kk][ty * 4];
            float4 b4 = *(const float4*)&Ws[kk][tx * 4];
            float a[4] = {a4.x, a4.y, a4.z, a4.w};
            float b[4] = {b4.x, b4.y, b4.z, b4.w};
            #pragma unroll
            for (int i = 0; i < 4; i++)
                #pragma unroll
                for (int j = 0; j < 4; j++)
                    acc[i][j] += a[i] * b[j];
        }
        __syncthreads();
    }

    #pragma unroll
    for (int i = 0; i < 4; i++) {
        #pragma unroll
        for (int j = 0; j < 4; j++) {
            int m = m0 + ty * 4 + i;
            int n = n0 + tx * 4 + j;
            if (head_split) {
                int b = m >> 11, s = m & (SS - 1);
                int h = n >> 6,  dh = n & 63;
                g_qh[0]; // no-op to keep symbols referenced paths simple
                C[(((size_t)(b * HH + h)) * SS + s) * DH + dh] = acc[i][j];
            } else {
                C[(size_t)m * N + n] = acc[i][j];
            }
        }
    }
}

// ---------------------------------------------------------------------------
// Attention scores + mask + softmax. One warp per query row, 4 rows/CTA.
// Scores for the full row (2048) live in smem; single global write of attn.
// smem: kt 32x65 (8.3KB) + ps 4x2048 (32KB) = ~41KB static.
// ---------------------------------------------------------------------------
__global__ __launch_bounds__(128) void attn_softmax_kernel(
    const float* __restrict__ Qh, const float* __restrict__ Kh,
    const int* __restrict__ mask, float* __restrict__ attn)
{
    __shared__ float kt[32][65];
    __shared__ float ps[4][SS];

    const int bh  = blockIdx.y;
    const int q0  = blockIdx.x * 4;
    const int tid = threadIdx.x;
    const int w   = tid >> 5, lane = tid & 31;

    // hoist q row into registers (warp-uniform broadcast loads)
    const float* Qrow = Qh + ((size_t)bh * SS + q0 + w) * DH;
    float qreg[64];
    #pragma unroll
    for (int d = 0; d < 64; d++) qreg[d] = Qrow[d];

    const float* Kb   = Kh + (size_t)bh * SS * DH;
    const int*   mrow = mask + (size_t)(q0 + w) * SS;

    const int r = tid >> 2;          // 0..31 : key row in tile
    const int c = (tid & 3) * 16;    // 0,16,32,48

    float mrun = -3.0e38f;

    for (int t = 0; t < 64; t++) {
        const int kb = t * 32;
        // cooperative K-tile load (32 keys x 64 dims), pad-65 for bank-free read
        const float* src = Kb + (size_t)(kb + r) * DH + c;
        float4 v0 = *(const float4*)(src + 0);
        float4 v1 = *(const float4*)(src + 4);
        float4 v2 = *(const float4*)(src + 8);
        float4 v3 = *(const float4*)(src + 12);
        float* dst = &kt[r][c];
        dst[0]=v0.x; dst[1]=v0.y; dst[2]=v0.z;  dst[3]=v0.w;
        dst[4]=v1.x; dst[5]=v1.y; dst[6]=v1.z;  dst[7]=v1.w;
        dst[8]=v2.x; dst[9]=v2.y; dst[10]=v2.z; dst[11]=v2.w;
        dst[12]=v3.x; dst[13]=v3.y; dst[14]=v3.z; dst[15]=v3.w;
        __syncthreads();

        float s = 0.f;
        #pragma unroll
        for (int d = 0; d < 64; d++) s += qreg[d] * kt[lane][d];
        s *= 0.125f;                               // 1/sqrt(DH)
        if (mrow[kb + lane] == 0) s = -1e34f;
        ps[w][kb + lane] = s;
        mrun = fmaxf(mrun, s);
        __syncthreads();
    }

    #pragma unroll
    for (int off = 16; off; off >>= 1)
        mrun = fmaxf(mrun, __shfl_xor_sync(0xffffffffu, mrun, off));

    float sum = 0.f;
    for (int k2 = lane; k2 < SS; k2 += 32) {
        float e = __expf(ps[w][k2] - mrun);
        ps[w][k2] = e;
        sum += e;
    }
    #pragma unroll
    for (int off = 16; off; off >>= 1)
        sum += __shfl_xor_sync(0xffffffffu, sum, off);

    const float inv = 1.f / sum;
    float* Ar = attn + ((size_t)bh * SS + q0 + w) * SS;
    for (int k2 = lane; k2 < SS; k2 += 32)
        Ar[k2] = ps[w][k2] * inv;
}

// ---------------------------------------------------------------------------
// ctx[b,s, h*64+dh] = sum_k attn[bh,q,k] * Vh[bh,k,dh]
// 64(q) x 64(dh) tile per CTA, k-tile 16.
// ---------------------------------------------------------------------------
__global__ __launch_bounds__(256) void ctx_kernel(
    const float* __restrict__ attn, const float* __restrict__ Vh,
    float* __restrict__ ctx)
{
    __shared__ float As[16][64];
    __shared__ float Bs[16][64];
    const int bh = blockIdx.y;
    const int q0 = blockIdx.x * 64;
    const int tid = threadIdx.x;
    const int tx = tid & 15, ty = tid >> 4;

    const float* Ab = attn + (size_t)bh * SS * SS;
    const float* Vb = Vh   + (size_t)bh * SS * DH;

    const int ar = tid >> 2,  ac = (tid & 3) * 4;    // attn: row 0..63, kk off
    const int br = tid >> 4,  bc = (tid & 15) * 4;   // V:    kk 0..15, col

    float acc[4][4] = {};

    for (int k0 = 0; k0 < SS; k0 += 16) {
        float4 va = *(const float4*)&Ab[(size_t)(q0 + ar) * SS + k0 + ac];
        As[ac + 0][ar] = va.x; As[ac + 1][ar] = va.y;
        As[ac + 2][ar] = va.z; As[ac + 3][ar] = va.w;
        float4 vb = *(const float4*)&Vb[(size_t)(k0 + br) * DH + bc];
        *(float4*)&Bs[br][bc] = vb;
        __syncthreads();
        #pragma unroll
        for (int kk = 0; kk < 16; kk++) {
            float4 a4 = *(const float4*)&As[kk][ty * 4];
            float4 b4 = *(const float4*)&Bs[kk][tx * 4];
            float a[4] = {a4.x, a4.y, a4.z, a4.w};
            float b[4] = {b4.x, b4.y, b4.z, b4.w};
            #pragma unroll
            for (int i = 0; i < 4; i++)
                #pragma unroll
                for (int j = 0; j < 4; j++)
                    acc[i][j] += a[i] * b[j];
        }
        __syncthreads();
    }

    const int b = bh >> 4, h = bh & 15;
    #pragma unroll
    for (int i = 0; i < 4; i++) {
        #pragma unroll
        for (int j = 0; j < 4; j++) {
            int s  = q0 + ty * 4 + i;
            int dh = tx * 4 + j;
            ctx[((size_t)(b * SS + s)) * DD + h * 64 + dh] = acc[i][j];
        }
    }
}

// ---------------------------------------------------------------------------
extern "C" void kernel_launch(void* const* d_in, const int* in_sizes, int n_in,
                              void* d_out, int out_size)
{
    const float* q    = (const float*)d_in[0];
    const float* k    = (const float*)d_in[1];
    const float* v    = (const float*)d_in[2];
    const int*   mask = (const int*)  d_in[3];
    const float* Wq   = (const float*)d_in[4];
    const float* Wk   = (const float*)d_in[5];
    const float* Wv   = (const float*)d_in[6];
    const float* Wo   = (const float*)d_in[7];

    float* out  = (float*)d_out;                    // [B,S,D] = 4194304 floats
    float* attn = out + (size_t)MM * DD;            // [B,H,S,S] follows

    float *qh, *kh, *vh, *ctx;
    cudaGetSymbolAddress((void**)&qh,  g_qh);
    cudaGetSymbolAddress((void**)&kh,  g_kh);
    cudaGetSymbolAddress((void**)&vh,  g_vh);
    cudaGetSymbolAddress((void**)&ctx, g_ctx);

    dim3 gproj(DD / 64, MM / 64);   // (16, 64)

    gemm_nt_kernel<<<gproj, 256>>>(q, Wq, qh, 1);
    gemm_nt_kernel<<<gproj, 256>>>(k, Wk, kh, 1);
    gemm_nt_kernel<<<gproj, 256>>>(v, Wv, vh, 1);

    attn_softmax_kernel<<<dim3(SS / 4, BH), 128>>>(qh, kh, mask, attn);

    ctx_kernel<<<dim3(SS / 64, BH), 256>>>(attn, vh, ctx);

    gemm_nt_kernel<<<gproj, 256>>>(ctx, Wo, out, 0);
}

// round 6
// speedup vs baseline: 2.0655x; 2.0655x over previous
#include <cuda_runtime.h>
#include <math.h>

// Problem constants
#define BB   2
#define SS   2048
#define DD   1024
#define HH   16
#define DH   64
#define MM   (BB*SS)     // 4096
#define BH   (BB*HH)     // 32

// Scratch (device globals: allocation-free)
__device__ float g_qh[(size_t)BH*SS*DH];   // [B,H,S,DH]
__device__ float g_kh[(size_t)BH*SS*DH];
__device__ float g_vh[(size_t)BH*SS*DH];
__device__ float g_ctx[(size_t)MM*DD];     // [B,S,D]

// ---------------------------------------------------------------------------
// helpers
// ---------------------------------------------------------------------------
__device__ __forceinline__ unsigned smem_u32(const void* p){
    unsigned r;
    asm("{ .reg .u64 t; cvta.to.shared.u64 t, %1; cvt.u32.u64 %0, t; }"
        : "=r"(r) : "l"(p));
    return r;
}
#define CP16(dst,src) asm volatile("cp.async.cg.shared.global [%0], [%1], 16;\n" :: "r"(dst), "l"(src))
#define CPCOMMIT()    asm volatile("cp.async.commit_group;\n")
#define CPWAIT(N)     asm volatile("cp.async.wait_group %0;\n" :: "n"(N))

// split fp32 -> tf32 hi + tf32 lo (3xTF32 trick)
__device__ __forceinline__ void split2(float x, unsigned &h, unsigned &l){
    unsigned hu; asm("cvt.rna.tf32.f32 %0, %1;" : "=r"(hu) : "f"(x));
    float lf = x - __uint_as_float(hu);
    unsigned lu; asm("cvt.rna.tf32.f32 %0, %1;" : "=r"(lu) : "f"(lf));
    h = hu; l = lu;
}

__device__ __forceinline__ void mma_tf32(float c[4],
    unsigned a0, unsigned a1, unsigned a2, unsigned a3,
    unsigned b0, unsigned b1)
{
    asm volatile("mma.sync.aligned.m16n8k8.row.col.f32.tf32.tf32.f32 "
        "{%0,%1,%2,%3}, {%4,%5,%6,%7}, {%8,%9}, {%0,%1,%2,%3};"
        : "+f"(c[0]), "+f"(c[1]), "+f"(c[2]), "+f"(c[3])
        : "r"(a0),"r"(a1),"r"(a2),"r"(a3),"r"(b0),"r"(b1));
}
// D += a*b in ~fp32 precision: al*bh + ah*bl + ah*bh
__device__ __forceinline__ void mma3(float c[4],
    const unsigned* ah, const unsigned* al,
    const unsigned* bh2, const unsigned* bl2)
{
    mma_tf32(c, al[0],al[1],al[2],al[3], bh2[0],bh2[1]);
    mma_tf32(c, ah[0],ah[1],ah[2],ah[3], bl2[0],bl2[1]);
    mma_tf32(c, ah[0],ah[1],ah[2],ah[3], bh2[0],bh2[1]);
}

// ---------------------------------------------------------------------------
// C = A[M,K] @ W[N,K]^T  (torch Linear), M=4096, N=K=1024, 3xTF32 MMA.
// CTA tile 128(M) x 64(N), k-tile 16, 256 threads = 8 warps (4m x 2n),
// warp tile 32x32. cp.async double-buffered smem.
// head_split=1 -> write C into [B,H,S,DH] layout.
// ---------------------------------------------------------------------------
__global__ __launch_bounds__(256) void proj_mma(
    const float* __restrict__ A, const float* __restrict__ W,
    float* __restrict__ C, int head_split)
{
    __shared__ float As[2][128][20];   // rowlen 20 floats (80B, 16B aligned, bank-perm)
    __shared__ float Ws[2][64][20];

    const int K = DD;
    const int tid  = threadIdx.x;
    const int lane = tid & 31, wid = tid >> 5;
    const int wm = wid >> 1, wn = wid & 1;
    const int g = lane >> 2, t = lane & 3;
    const int m0 = blockIdx.y * 128, n0 = blockIdx.x * 64;

    float acc[2][4][4];
    #pragma unroll
    for (int i = 0; i < 2; i++)
        #pragma unroll
        for (int j = 0; j < 4; j++)
            #pragma unroll
            for (int e = 0; e < 4; e++) acc[i][j][e] = 0.f;

    // stage prefetch (cp.async): A 128x16 (512 chunks), W 64x16 (256 chunks)
    auto prefetch = [&](int kt, int s){
        const int k0 = kt * 16;
        #pragma unroll
        for (int i = 0; i < 2; i++){
            int idx = tid + i * 256;
            int r = idx >> 2, c = idx & 3;
            CP16(smem_u32(&As[s][r][c*4]), &A[(size_t)(m0 + r) * K + k0 + c*4]);
        }
        {
            int r = tid >> 2, c = tid & 3;
            CP16(smem_u32(&Ws[s][r][c*4]), &W[(size_t)(n0 + r) * K + k0 + c*4]);
        }
        CPCOMMIT();
    };

    prefetch(0, 0);
    const int NT = K / 16;  // 64
    for (int kt = 0; kt < NT; kt++){
        const int s = kt & 1;
        if (kt + 1 < NT){ prefetch(kt + 1, s ^ 1); CPWAIT(1); }
        else            { CPWAIT(0); }
        __syncthreads();

        #pragma unroll
        for (int ks = 0; ks < 2; ks++){
            const int k0 = ks * 8;
            unsigned ah[2][4], al[2][4];
            #pragma unroll
            for (int mt = 0; mt < 2; mt++){
                const int mb = wm * 32 + mt * 16;
                split2(As[s][mb + g    ][k0 + t    ], ah[mt][0], al[mt][0]);
                split2(As[s][mb + 8 + g][k0 + t    ], ah[mt][1], al[mt][1]);
                split2(As[s][mb + g    ][k0 + t + 4], ah[mt][2], al[mt][2]);
                split2(As[s][mb + 8 + g][k0 + t + 4], ah[mt][3], al[mt][3]);
            }
            unsigned bh[4][2], bl[4][2];
            #pragma unroll
            for (int nt = 0; nt < 4; nt++){
                const int nb = wn * 32 + nt * 8;
                split2(Ws[s][nb + g][k0 + t    ], bh[nt][0], bl[nt][0]);
                split2(Ws[s][nb + g][k0 + t + 4], bh[nt][1], bl[nt][1]);
            }
            #pragma unroll
            for (int mt = 0; mt < 2; mt++)
                #pragma unroll
                for (int nt = 0; nt < 4; nt++)
                    mma3(acc[mt][nt], ah[mt], al[mt], bh[nt], bl[nt]);
        }
        __syncthreads();
    }

    // epilogue
    #pragma unroll
    for (int mt = 0; mt < 2; mt++){
        #pragma unroll
        for (int nt = 0; nt < 4; nt++){
            const int r0 = m0 + wm * 32 + mt * 16 + g;
            const int r1 = r0 + 8;
            const int cb = n0 + wn * 32 + nt * 8 + 2 * t;
            if (head_split){
                #pragma unroll
                for (int e = 0; e < 4; e++){
                    int m = (e < 2) ? r0 : r1;
                    int n = cb + (e & 1);
                    int b = m >> 11, sq = m & (SS - 1);
                    int h = n >> 6,  dh = n & 63;
                    C[(((size_t)(b * HH + h)) * SS + sq) * DH + dh] = acc[mt][nt][e];
                }
            } else {
                C[(size_t)r0 * DD + cb    ] = acc[mt][nt][0];
                C[(size_t)r0 * DD + cb + 1] = acc[mt][nt][1];
                C[(size_t)r1 * DD + cb    ] = acc[mt][nt][2];
                C[(size_t)r1 * DD + cb + 1] = acc[mt][nt][3];
            }
        }
    }
}

// ---------------------------------------------------------------------------
// Scores + mask + softmax, fused, MMA-based.
// CTA = 16 query rows x all 2048 keys (full score rows in smem -> one pass,
// single global write of attn). 256 threads = 8 warps, each warp owns 16 keys
// per 128-key block; K blocks cp.async double-buffered.
// Dynamic smem: ps[16][2052] + qs[16][68] + ks[2][128][68] + invs[16] ~201KB
// ---------------------------------------------------------------------------
#define PSL 2052
#define SC_SMEM_FLOATS (16*PSL + 16*68 + 2*128*68 + 16)

__global__ __launch_bounds__(256) void scores_softmax(
    const float* __restrict__ Qh, const float* __restrict__ Kh,
    const int* __restrict__ mask, float* __restrict__ attn)
{
    extern __shared__ float sm[];
    float* ps   = sm;                       // [16][PSL]
    float* qs   = ps + 16 * PSL;            // [16][68]
    float* ks   = qs + 16 * 68;             // [2][128][68]
    float* invs = ks + 2 * 128 * 68;        // [16]

    const int tid  = threadIdx.x;
    const int lane = tid & 31, wid = tid >> 5;
    const int g = lane >> 2, t = lane & 3;
    const int bh = blockIdx.y, q0 = blockIdx.x * 16;

    const float* Qb = Qh + ((size_t)bh * SS + q0) * DH;
    const float* Kb = Kh + (size_t)bh * SS * DH;

    // load Q tile 16x64 -> qs
    {
        int r = tid >> 4, c = tid & 15;   // 256 f4 total
        *(float4*)&qs[r * 68 + c * 4] = *(const float4*)&Qb[(size_t)r * DH + c * 4];
    }
    __syncthreads();

    // Q fragments (held in registers, hi+lo, for all 8 k-steps)
    unsigned qah[8][4], qal[8][4];
    #pragma unroll
    for (int ks8 = 0; ks8 < 8; ks8++){
        const int k0 = ks8 * 8;
        split2(qs[(g    ) * 68 + k0 + t    ], qah[ks8][0], qal[ks8][0]);
        split2(qs[(g + 8) * 68 + k0 + t    ], qah[ks8][1], qal[ks8][1]);
        split2(qs[(g    ) * 68 + k0 + t + 4], qah[ks8][2], qal[ks8][2]);
        split2(qs[(g + 8) * 68 + k0 + t + 4], qah[ks8][3], qal[ks8][3]);
    }

    auto pre = [&](int kb, int s){
        float* dst = ks + s * 128 * 68;
        #pragma unroll
        for (int i = 0; i < 8; i++){
            int idx = tid + i * 256;        // 2048 chunks
            int r = idx >> 4, c = idx & 15;
            CP16(smem_u32(&dst[r * 68 + c * 4]),
                 &Kb[(size_t)(kb * 128 + r) * DH + c * 4]);
        }
        CPCOMMIT();
    };

    pre(0, 0);
    const int nbase = wid * 16;   // 8 warps x 16 keys = 128
    for (int kb = 0; kb < 16; kb++){
        const int s = kb & 1;
        if (kb + 1 < 16){ pre(kb + 1, s ^ 1); CPWAIT(1); }
        else            { CPWAIT(0); }
        __syncthreads();

        const float* kbuf = ks + s * 128 * 68;
        float acc[2][4] = {{0.f,0.f,0.f,0.f},{0.f,0.f,0.f,0.f}};
        #pragma unroll
        for (int ks8 = 0; ks8 < 8; ks8++){
            const int k0 = ks8 * 8;
            unsigned bhf[2][2], blf[2][2];
            #pragma unroll
            for (int nt = 0; nt < 2; nt++){
                const int nb = nbase + nt * 8;
                split2(kbuf[(nb + g) * 68 + k0 + t    ], bhf[nt][0], blf[nt][0]);
                split2(kbuf[(nb + g) * 68 + k0 + t + 4], bhf[nt][1], blf[nt][1]);
            }
            #pragma unroll
            for (int nt = 0; nt < 2; nt++)
                mma3(acc[nt], qah[ks8], qal[ks8], bhf[nt], blf[nt]);
        }
        // write scaled scores to ps
        #pragma unroll
        for (int nt = 0; nt < 2; nt++){
            const int col = kb * 128 + nbase + nt * 8 + 2 * t;
            ps[(g    ) * PSL + col    ] = acc[nt][0] * 0.125f;
            ps[(g    ) * PSL + col + 1] = acc[nt][1] * 0.125f;
            ps[(g + 8) * PSL + col    ] = acc[nt][2] * 0.125f;
            ps[(g + 8) * PSL + col + 1] = acc[nt][3] * 0.125f;
        }
        __syncthreads();   // all warps done with kbuf before next prefetch into it
    }

    // --- softmax: 16 threads per row ---
    const int row = tid >> 4, sub = tid & 15;
    const int* mrow = mask + (size_t)(q0 + row) * SS;
    float* pr = ps + row * PSL;

    float mx = -3.0e38f;
    for (int k2 = sub; k2 < SS; k2 += 16){
        float sv = pr[k2];
        if (mrow[k2] == 0) sv = -1e34f;
        pr[k2] = sv;
        mx = fmaxf(mx, sv);
    }
    #pragma unroll
    for (int off = 1; off < 16; off <<= 1)
        mx = fmaxf(mx, __shfl_xor_sync(0xffffffffu, mx, off));

    float sum = 0.f;
    for (int k2 = sub; k2 < SS; k2 += 16){
        float e = __expf(pr[k2] - mx);
        pr[k2] = e;
        sum += e;
    }
    #pragma unroll
    for (int off = 1; off < 16; off <<= 1)
        sum += __shfl_xor_sync(0xffffffffu, sum, off);

    if (sub == 0) invs[row] = 1.f / sum;
    __syncthreads();

    // coalesced attn write
    float* Ar = attn + ((size_t)bh * SS + q0) * SS;
    #pragma unroll
    for (int i = 0; i < 32; i++){
        int idx = tid + i * 256;          // 8192 f4
        int r = idx >> 9, c4 = idx & 511;
        float inv = invs[r];
        float4 v = *(float4*)&ps[r * PSL + c4 * 4];
        v.x *= inv; v.y *= inv; v.z *= inv; v.w *= inv;
        *(float4*)&Ar[(size_t)r * SS + c4 * 4] = v;
    }
}

// ---------------------------------------------------------------------------
// ctx[b,s,h*64+dh] = sum_k attn[bh,q,k] * Vh[bh,k,dh], 3xTF32 MMA.
// CTA 128(q) x 64(dh), k-tile 16, 256 threads = 8 warps (4m x 2n), warp 32x32.
// ---------------------------------------------------------------------------
__global__ __launch_bounds__(256) void ctx_mma(
    const float* __restrict__ attn, const float* __restrict__ Vh,
    float* __restrict__ ctx)
{
    __shared__ float Ps[2][128][20];
    __shared__ float Vs[2][16][72];   // rowlen 72 -> conflict-free B frags

    const int tid  = threadIdx.x;
    const int lane = tid & 31, wid = tid >> 5;
    const int wm = wid >> 1, wn = wid & 1;
    const int g = lane >> 2, t = lane & 3;
    const int bh = blockIdx.y, q0 = blockIdx.x * 128;

    const float* Ab = attn + (size_t)bh * SS * SS;
    const float* Vb = Vh   + (size_t)bh * SS * DH;

    float acc[2][4][4];
    #pragma unroll
    for (int i = 0; i < 2; i++)
        #pragma unroll
        for (int j = 0; j < 4; j++)
            #pragma unroll
            for (int e = 0; e < 4; e++) acc[i][j][e] = 0.f;

    auto prefetch = [&](int kt, int s){
        #pragma unroll
        for (int i = 0; i < 2; i++){
            int idx = tid + i * 256;
            int r = idx >> 2, c = idx & 3;
            CP16(smem_u32(&Ps[s][r][c*4]),
                 &Ab[(size_t)(q0 + r) * SS + kt * 16 + c*4]);
        }
        {
            int r = tid >> 4, c = tid & 15;
            CP16(smem_u32(&Vs[s][r][c*4]),
                 &Vb[(size_t)(kt * 16 + r) * DH + c*4]);
        }
        CPCOMMIT();
    };

    prefetch(0, 0);
    const int NT = SS / 16;   // 128
    for (int kt = 0; kt < NT; kt++){
        const int s = kt & 1;
        if (kt + 1 < NT){ prefetch(kt + 1, s ^ 1); CPWAIT(1); }
        else            { CPWAIT(0); }
        __syncthreads();

        #pragma unroll
        for (int ks = 0; ks < 2; ks++){
            const int k0 = ks * 8;
            unsigned ah[2][4], al[2][4];
            #pragma unroll
            for (int mt = 0; mt < 2; mt++){
                const int mb = wm * 32 + mt * 16;
                split2(Ps[s][mb + g    ][k0 + t    ], ah[mt][0], al[mt][0]);
                split2(Ps[s][mb + 8 + g][k0 + t    ], ah[mt][1], al[mt][1]);
                split2(Ps[s][mb + g    ][k0 + t + 4], ah[mt][2], al[mt][2]);
                split2(Ps[s][mb + 8 + g][k0 + t + 4], ah[mt][3], al[mt][3]);
            }
            unsigned bhf[4][2], blf[4][2];
            #pragma unroll
            for (int nt = 0; nt < 4; nt++){
                const int nb = wn * 32 + nt * 8;
                split2(Vs[s][k0 + t    ][nb + g], bhf[nt][0], blf[nt][0]);
                split2(Vs[s][k0 + t + 4][nb + g], bhf[nt][1], blf[nt][1]);
            }
            #pragma unroll
            for (int mt = 0; mt < 2; mt++)
                #pragma unroll
                for (int nt = 0; nt < 4; nt++)
                    mma3(acc[mt][nt], ah[mt], al[mt], bhf[nt], blf[nt]);
        }
        __syncthreads();
    }

    const int b = bh >> 4, h = bh & 15;
    #pragma unroll
    for (int mt = 0; mt < 2; mt++){
        #pragma unroll
        for (int nt = 0; nt < 4; nt++){
            const int r0 = q0 + wm * 32 + mt * 16 + g;
            const int r1 = r0 + 8;
            const int cb = h * 64 + wn * 32 + nt * 8 + 2 * t;
            ctx[((size_t)(b * SS + r0)) * DD + cb    ] = acc[mt][nt][0];
            ctx[((size_t)(b * SS + r0)) * DD + cb + 1] = acc[mt][nt][1];
            ctx[((size_t)(b * SS + r1)) * DD + cb    ] = acc[mt][nt][2];
            ctx[((size_t)(b * SS + r1)) * DD + cb + 1] = acc[mt][nt][3];
        }
    }
}

// ---------------------------------------------------------------------------
extern "C" void kernel_launch(void* const* d_in, const int* in_sizes, int n_in,
                              void* d_out, int out_size)
{
    const float* q    = (const float*)d_in[0];
    const float* k    = (const float*)d_in[1];
    const float* v    = (const float*)d_in[2];
    const int*   mask = (const int*)  d_in[3];
    const float* Wq   = (const float*)d_in[4];
    const float* Wk   = (const float*)d_in[5];
    const float* Wv   = (const float*)d_in[6];
    const float* Wo   = (const float*)d_in[7];

    float* out  = (float*)d_out;                    // [B,S,D]
    float* attn = out + (size_t)MM * DD;            // [B,H,S,S]

    float *qh, *kh, *vh, *ctx;
    cudaGetSymbolAddress((void**)&qh,  g_qh);
    cudaGetSymbolAddress((void**)&kh,  g_kh);
    cudaGetSymbolAddress((void**)&vh,  g_vh);
    cudaGetSymbolAddress((void**)&ctx, g_ctx);

    const int sc_smem = SC_SMEM_FLOATS * (int)sizeof(float);   // ~205KB
    cudaFuncSetAttribute(scores_softmax,
                         cudaFuncAttributeMaxDynamicSharedMemorySize, sc_smem);

    dim3 gproj(DD / 64, MM / 128);   // (16, 32)

    proj_mma<<<gproj, 256>>>(q, Wq, qh, 1);
    proj_mma<<<gproj, 256>>>(k, Wk, kh, 1);
    proj_mma<<<gproj, 256>>>(v, Wv, vh, 1);

    scores_softmax<<<dim3(SS / 16, BH), 256, sc_smem>>>(qh, kh, mask, attn);

    ctx_mma<<<dim3(SS / 128, BH), 256>>>(attn, vh, ctx);

    proj_mma<<<gproj, 256>>>(ctx, Wo, out, 0);
}

// round 7
// speedup vs baseline: 3.1931x; 1.5459x over previous
#include <cuda_runtime.h>
#include <cuda_bf16.h>
#include <math.h>

// Problem constants
#define BB   2
#define SS   2048
#define DD   1024
#define HH   16
#define DH   64
#define MM   (BB*SS)     // 4096
#define BH   (BB*HH)     // 32

typedef __nv_bfloat16 bf16;
typedef unsigned uns;

// ---------------------------------------------------------------------------
// Scratch arena (device globals: allocation-free). Offsets in bf16 elements.
// 14 chunks of 4M elems (inputs/activations) + 8 chunks of 1M (weights).
// ---------------------------------------------------------------------------
#define CHK (1u<<22)            // 4194304 elems
#define WCH (1u<<20)            // 1048576 elems
__device__ bf16 g_bf[(size_t)14*CHK + 8*WCH];     // 128MB + 16MB
__device__ unsigned g_mbits[(size_t)SS*SS/32];

// arena layout (elem offsets):
// 0:xa_h 1:xa_l 2:xb_h 3:xb_l 4:xc_h 5:xc_l          (split q,k,v inputs [M,K])
// 6:qh_h 7:qh_l 8:kh_h 9:kh_l                        (head-split [BH,S,DH])
// 10:vt_h 11:vt_l                                    (V transposed [BH,DH,S])
// 12:cx_h 13:cx_l                                    (ctx [M,D])
// then weights: wq_h,wq_l,wk_h,wk_l,wv_h,wv_l,wo_h,wo_l  ([N,K])

// ---------------------------------------------------------------------------
// helpers
// ---------------------------------------------------------------------------
__device__ __forceinline__ unsigned smem_u32(const void* p){
    unsigned r;
    asm("{ .reg .u64 t; cvta.to.shared.u64 t, %1; cvt.u32.u64 %0, t; }"
        : "=r"(r) : "l"(p));
    return r;
}
#define CP16(dst,src) asm volatile("cp.async.cg.shared.global [%0], [%1], 16;\n" :: "r"(dst), "l"(src))
#define CPCOMMIT()    asm volatile("cp.async.commit_group;\n")
#define CPWAIT(N)     asm volatile("cp.async.wait_group %0;\n" :: "n"(N))

__device__ __forceinline__ void bsplit(float x, bf16 &h, bf16 &l){
    h = __float2bfloat16(x);
    l = __float2bfloat16(x - __bfloat162float(h));
}
__device__ __forceinline__ uns pk(bf16 a, bf16 b){
    return (uns)__bfloat16_as_ushort(a) | ((uns)__bfloat16_as_ushort(b) << 16);
}
// split two consecutive-k fp32 values -> packed hi reg + packed lo reg
__device__ __forceinline__ void bsplit2(float x, float y, uns &h, uns &l){
    bf16 hx,lx,hy,ly; bsplit(x,hx,lx); bsplit(y,hy,ly);
    h = pk(hx,hy); l = pk(lx,ly);
}

__device__ __forceinline__ void mma_bf16(float c[4], const uns a[4], const uns b[2]){
    asm volatile("mma.sync.aligned.m16n8k16.row.col.f32.bf16.bf16.f32 "
        "{%0,%1,%2,%3}, {%4,%5,%6,%7}, {%8,%9}, {%0,%1,%2,%3};"
        : "+f"(c[0]),"+f"(c[1]),"+f"(c[2]),"+f"(c[3])
        : "r"(a[0]),"r"(a[1]),"r"(a[2]),"r"(a[3]),"r"(b[0]),"r"(b[1]));
}
// compensated: c += al*bh + ah*bl + ah*bh
__device__ __forceinline__ void mma3b(float c[4], const uns ah[4], const uns al[4],
                                      const uns bh[2], const uns bl[2]){
    mma_bf16(c, al, bh);
    mma_bf16(c, ah, bl);
    mma_bf16(c, ah, bh);
}

// ---------------------------------------------------------------------------
// fp32 -> bf16 hi/lo planes (elementwise, 4 elems/thread)
// ---------------------------------------------------------------------------
__global__ __launch_bounds__(256) void split_kernel(
    const float* __restrict__ x, bf16* __restrict__ hi, bf16* __restrict__ lo)
{
    int i = (blockIdx.x * 256 + threadIdx.x) * 4;
    float4 v = *(const float4*)(x + i);
    bf16 h0,l0,h1,l1,h2,l2,h3,l3;
    bsplit(v.x,h0,l0); bsplit(v.y,h1,l1); bsplit(v.z,h2,l2); bsplit(v.w,h3,l3);
    *(uint2*)(hi + i) = make_uint2(pk(h0,h1), pk(h2,h3));
    *(uint2*)(lo + i) = make_uint2(pk(l0,l1), pk(l2,l3));
}

// bit-pack mask
__global__ __launch_bounds__(256) void maskpack_kernel(const int* __restrict__ mask)
{
    int i = blockIdx.x * 256 + threadIdx.x;
    unsigned w = __ballot_sync(0xffffffffu, mask[i] != 0);
    if ((threadIdx.x & 31) == 0) g_mbits[i >> 5] = w;
}

// ---------------------------------------------------------------------------
// C = A[M,K] @ W[N,K]^T, bf16x3. CTA 128x64, k-tile 32, 256 thr, warp 32x32.
// mode 0: fp32 flat [M,DD].  mode 1: split head-split [BH,S,DH].
// mode 2: split transposed head-split [BH,DH,S]  (for V).
// dyn smem: A[2buf][2pl][128][40] + W[2][2][64][40] bf16 = 61440B
// ---------------------------------------------------------------------------
__global__ __launch_bounds__(256) void proj_bf16(
    const bf16* __restrict__ Ah_g, const bf16* __restrict__ Al_g,
    const bf16* __restrict__ Wh_g, const bf16* __restrict__ Wl_g,
    float* __restrict__ Cf, bf16* __restrict__ Ch, bf16* __restrict__ Cl,
    int mode)
{
    extern __shared__ __align__(16) unsigned char dynsm[];
    bf16* sA = (bf16*)dynsm;               // 20480 elems
    bf16* sW = sA + 2*2*128*40;            // 10240 elems

    const int K = DD;
    const int tid = threadIdx.x, lane = tid & 31, wid = tid >> 5;
    const int wm = wid >> 1, wn = wid & 1;
    const int g = lane >> 2, t = lane & 3;
    const int m0 = blockIdx.y * 128, n0 = blockIdx.x * 64;

    float acc[2][4][4];
    #pragma unroll
    for (int i=0;i<2;i++)
        #pragma unroll
        for (int j=0;j<4;j++)
            #pragma unroll
            for (int e=0;e<4;e++) acc[i][j][e]=0.f;

    auto pre = [&](int kt, int s){
        const int k0 = kt * 32;
        #pragma unroll
        for (int i = 0; i < 4; i++){                 // A: 1024 chunks
            int idx = tid + i*256;
            int pl = idx >> 9, j = idx & 511;
            int r = j >> 2, c = j & 3;
            const bf16* src = (pl ? Al_g : Ah_g) + (size_t)(m0+r)*K + k0 + c*8;
            CP16(smem_u32(sA + ((s*2+pl)*128 + r)*40 + c*8), src);
        }
        #pragma unroll
        for (int i = 0; i < 2; i++){                 // W: 512 chunks
            int idx = tid + i*256;
            int pl = idx >> 8, j = idx & 255;
            int r = j >> 2, c = j & 3;
            const bf16* src = (pl ? Wl_g : Wh_g) + (size_t)(n0+r)*K + k0 + c*8;
            CP16(smem_u32(sW + ((s*2+pl)*64 + r)*40 + c*8), src);
        }
        CPCOMMIT();
    };

    pre(0, 0);
    const int NT = K / 32;   // 32
    for (int kt = 0; kt < NT; kt++){
        const int s = kt & 1;
        if (kt + 1 < NT){ pre(kt + 1, s ^ 1); CPWAIT(1); }
        else            { CPWAIT(0); }
        __syncthreads();

        const bf16* Ahs = sA + (s*2+0)*128*40;
        const bf16* Als = sA + (s*2+1)*128*40;
        const bf16* Whs = sW + (s*2+0)*64*40;
        const bf16* Wls = sW + (s*2+1)*64*40;

        #pragma unroll
        for (int ks = 0; ks < 2; ks++){
            const int k0 = ks*16 + 2*t;
            uns ah[2][4], al[2][4];
            #pragma unroll
            for (int mt = 0; mt < 2; mt++){
                int r0 = (wm*32 + mt*16 + g)*40;
                int r1 = r0 + 8*40;
                ah[mt][0] = *(const uns*)(Ahs + r0 + k0);
                ah[mt][1] = *(const uns*)(Ahs + r1 + k0);
                ah[mt][2] = *(const uns*)(Ahs + r0 + k0 + 8);
                ah[mt][3] = *(const uns*)(Ahs + r1 + k0 + 8);
                al[mt][0] = *(const uns*)(Als + r0 + k0);
                al[mt][1] = *(const uns*)(Als + r1 + k0);
                al[mt][2] = *(const uns*)(Als + r0 + k0 + 8);
                al[mt][3] = *(const uns*)(Als + r1 + k0 + 8);
            }
            uns bh[4][2], bl[4][2];
            #pragma unroll
            for (int nt = 0; nt < 4; nt++){
                int rn = (wn*32 + nt*8 + g)*40;
                bh[nt][0] = *(const uns*)(Whs + rn + k0);
                bh[nt][1] = *(const uns*)(Whs + rn + k0 + 8);
                bl[nt][0] = *(const uns*)(Wls + rn + k0);
                bl[nt][1] = *(const uns*)(Wls + rn + k0 + 8);
            }
            #pragma unroll
            for (int mt = 0; mt < 2; mt++)
                #pragma unroll
                for (int nt = 0; nt < 4; nt++)
                    mma3b(acc[mt][nt], ah[mt], al[mt], bh[nt], bl[nt]);
        }
        __syncthreads();
    }

    #pragma unroll
    for (int mt = 0; mt < 2; mt++){
        #pragma unroll
        for (int nt = 0; nt < 4; nt++){
            const int r0 = m0 + wm*32 + mt*16 + g;
            const int r1 = r0 + 8;
            const int cb = n0 + wn*32 + nt*8 + 2*t;
            float* a = acc[mt][nt];
            if (mode == 0){
                *(float2*)&Cf[(size_t)r0*DD + cb] = make_float2(a[0], a[1]);
                *(float2*)&Cf[(size_t)r1*DD + cb] = make_float2(a[2], a[3]);
            } else {
                #pragma unroll
                for (int e = 0; e < 4; e++){
                    int m = (e < 2) ? r0 : r1;
                    int n = cb + (e & 1);
                    int b = m >> 11, sq = m & (SS - 1);
                    int h = n >> 6,  dh = n & 63;
                    size_t idx = (mode == 1)
                        ? (((size_t)(b*HH + h))*SS + sq)*DH + dh
                        : (((size_t)(b*HH + h))*DH + dh)*SS + sq;
                    bf16 hh, ll; bsplit(a[e], hh, ll);
                    Ch[idx] = hh; Cl[idx] = ll;
                }
            }
        }
    }
}

// ---------------------------------------------------------------------------
// Fused scores + mask + softmax, bf16x3 MMA, pre-split Q/K planes.
// CTA = 16 q rows x 2048 keys, full score rows in smem, 256 thr (8 warps),
// warp owns 16 keys per 128-key block, double-buffered cp.async K tiles.
// dyn smem: ps[16][2052]f32 + q[2][16][72]bf16 + k[2][2][128][72]bf16 + invs
// ---------------------------------------------------------------------------
#define SC_SMEM (16*2052*4 + 2*16*72*2 + 2*2*128*72*2 + 64)   // 209728 B

__global__ __launch_bounds__(256) void scores_softmax(
    const bf16* __restrict__ Qh_g, const bf16* __restrict__ Ql_g,
    const bf16* __restrict__ Kh_g, const bf16* __restrict__ Kl_g,
    float* __restrict__ attn)
{
    extern __shared__ __align__(16) unsigned char dynsm[];
    float* ps  = (float*)dynsm;                                    // 16x2052
    bf16* qsm  = (bf16*)(dynsm + 16*2052*4);                       // [2][16][72]
    bf16* ksm  = (bf16*)(dynsm + 16*2052*4 + 2*16*72*2);           // [2][2][128][72]
    float* invs= (float*)(dynsm + 16*2052*4 + 2*16*72*2 + 2*2*128*72*2);

    const int tid = threadIdx.x, lane = tid & 31, wid = tid >> 5;
    const int g = lane >> 2, t = lane & 3;
    const int bh = blockIdx.y, q0 = blockIdx.x * 16;

    // stage Q tile (16x64, both planes) - 256 chunks, 1 per thread
    {
        int pl = tid >> 7, j = tid & 127;
        int r = j >> 3, c = j & 7;
        const bf16* src = (pl ? Ql_g : Qh_g) + ((size_t)bh*SS + q0 + r)*DH + c*8;
        CP16(smem_u32(qsm + (pl*16 + r)*72 + c*8), src);
    }

    auto pre = [&](int kb, int s){
        #pragma unroll
        for (int i = 0; i < 8; i++){            // 2048 chunks
            int idx = tid + i*256;
            int pl = idx >> 10, j = idx & 1023;
            int r = j >> 3, c = j & 7;
            const bf16* src = (pl ? Kl_g : Kh_g)
                            + ((size_t)bh*SS + kb*128 + r)*DH + c*8;
            CP16(smem_u32(ksm + ((s*2+pl)*128 + r)*72 + c*8), src);
        }
        CPCOMMIT();
    };

    pre(0, 0);   // commits Q staging + K block 0 together

    uns qah[4][4], qal[4][4];
    const int nbase = wid * 16;

    for (int kb = 0; kb < 16; kb++){
        const int s = kb & 1;
        if (kb + 1 < 16){ pre(kb + 1, s ^ 1); CPWAIT(1); }
        else            { CPWAIT(0); }
        __syncthreads();

        if (kb == 0){
            #pragma unroll
            for (int ck = 0; ck < 4; ck++){
                int k0 = ck*16 + 2*t;
                qah[ck][0] = *(const uns*)(qsm + (g    )*72 + k0);
                qah[ck][1] = *(const uns*)(qsm + (g + 8)*72 + k0);
                qah[ck][2] = *(const uns*)(qsm + (g    )*72 + k0 + 8);
                qah[ck][3] = *(const uns*)(qsm + (g + 8)*72 + k0 + 8);
                qal[ck][0] = *(const uns*)(qsm + (16 + g    )*72 + k0);
                qal[ck][1] = *(const uns*)(qsm + (16 + g + 8)*72 + k0);
                qal[ck][2] = *(const uns*)(qsm + (16 + g    )*72 + k0 + 8);
                qal[ck][3] = *(const uns*)(qsm + (16 + g + 8)*72 + k0 + 8);
            }
        }

        const bf16* khs = ksm + (s*2+0)*128*72;
        const bf16* kls = ksm + (s*2+1)*128*72;
        float acc[2][4] = {{0.f,0.f,0.f,0.f},{0.f,0.f,0.f,0.f}};

        #pragma unroll
        for (int ck = 0; ck < 4; ck++){
            int k0 = ck*16 + 2*t;
            uns bhf[2][2], blf[2][2];
            #pragma unroll
            for (int nt = 0; nt < 2; nt++){
                int rn = (nbase + nt*8 + g)*72;
                bhf[nt][0] = *(const uns*)(khs + rn + k0);
                bhf[nt][1] = *(const uns*)(khs + rn + k0 + 8);
                blf[nt][0] = *(const uns*)(kls + rn + k0);
                blf[nt][1] = *(const uns*)(kls + rn + k0 + 8);
            }
            mma3b(acc[0], qah[ck], qal[ck], bhf[0], blf[0]);
            mma3b(acc[1], qah[ck], qal[ck], bhf[1], blf[1]);
        }

        #pragma unroll
        for (int nt = 0; nt < 2; nt++){
            int col = kb*128 + nbase + nt*8 + 2*t;
            ps[(g    )*2052 + col    ] = acc[nt][0] * 0.125f;
            ps[(g    )*2052 + col + 1] = acc[nt][1] * 0.125f;
            ps[(g + 8)*2052 + col    ] = acc[nt][2] * 0.125f;
            ps[(g + 8)*2052 + col + 1] = acc[nt][3] * 0.125f;
        }
        __syncthreads();
    }

    // softmax: 16 threads per row, bit-packed mask
    const int row = tid >> 4, sub = tid & 15;
    const unsigned* mb = g_mbits + (((size_t)(q0 + row)) * SS >> 5);
    float* pr = ps + row * 2052;

    float mx = -3.0e38f;
    for (int k2 = sub; k2 < SS; k2 += 16){
        float sv = pr[k2];
        unsigned w = mb[k2 >> 5];
        if (!((w >> (k2 & 31)) & 1)) sv = -1e34f;
        pr[k2] = sv;
        mx = fmaxf(mx, sv);
    }
    #pragma unroll
    for (int off = 1; off < 16; off <<= 1)
        mx = fmaxf(mx, __shfl_xor_sync(0xffffffffu, mx, off));

    float sum = 0.f;
    for (int k2 = sub; k2 < SS; k2 += 16){
        float e = __expf(pr[k2] - mx);
        pr[k2] = e;
        sum += e;
    }
    #pragma unroll
    for (int off = 1; off < 16; off <<= 1)
        sum += __shfl_xor_sync(0xffffffffu, sum, off);

    if (sub == 0) invs[row] = 1.f / sum;
    __syncthreads();

    float* Ar = attn + ((size_t)bh * SS + q0) * SS;
    #pragma unroll
    for (int i = 0; i < 32; i++){
        int idx = tid + i * 256;
        int r = idx >> 9, c4 = idx & 511;
        float inv = invs[r];
        float4 v = *(float4*)&ps[r * 2052 + c4 * 4];
        v.x *= inv; v.y *= inv; v.z *= inv; v.w *= inv;
        *(float4*)&Ar[(size_t)r * SS + c4 * 4] = v;
    }
}

// ---------------------------------------------------------------------------
// ctx = attn @ V  (bf16x3; P split on the fly, V pre-split transposed planes)
// CTA 128(q) x 64(dh), k-tile 32. Output: split ctx planes [M,DD].
// dyn smem: Ps[2][128][40]f32 + Vs[2][2][64][40]bf16 = 61440B
// ---------------------------------------------------------------------------
__global__ __launch_bounds__(256) void ctx_mma(
    const float* __restrict__ attn,
    const bf16* __restrict__ Vh_g, const bf16* __restrict__ Vl_g,
    bf16* __restrict__ Ch, bf16* __restrict__ Cl)
{
    extern __shared__ __align__(16) unsigned char dynsm[];
    float* Ps = (float*)dynsm;                 // [2][128][40]
    bf16*  Vs = (bf16*)(dynsm + 2*128*40*4);   // [2][2][64][40]

    const int tid = threadIdx.x, lane = tid & 31, wid = tid >> 5;
    const int wm = wid >> 1, wn = wid & 1;
    const int g = lane >> 2, t = lane & 3;
    const int bh = blockIdx.y, q0 = blockIdx.x * 128;

    const float* Ab  = attn + (size_t)bh * SS * SS;
    const bf16*  Vhb = Vh_g + (size_t)bh * DH * SS;
    const bf16*  Vlb = Vl_g + (size_t)bh * DH * SS;

    float acc[2][4][4];
    #pragma unroll
    for (int i=0;i<2;i++)
        #pragma unroll
        for (int j=0;j<4;j++)
            #pragma unroll
            for (int e=0;e<4;e++) acc[i][j][e]=0.f;

    auto pre = [&](int kt, int s){
        const int k0 = kt * 32;
        #pragma unroll
        for (int i = 0; i < 4; i++){           // P: 1024 chunks (4 f32 each)
            int idx = tid + i*256;
            int r = idx >> 3, c = idx & 7;
            CP16(smem_u32(Ps + (s*128 + r)*40 + c*4),
                 Ab + (size_t)(q0 + r)*SS + k0 + c*4);
        }
        #pragma unroll
        for (int i = 0; i < 2; i++){           // V: 512 chunks (8 bf16 each)
            int idx = tid + i*256;
            int pl = idx >> 8, j = idx & 255;
            int r = j >> 2, c = j & 3;
            const bf16* src = (pl ? Vlb : Vhb) + (size_t)r*SS + k0 + c*8;
            CP16(smem_u32(Vs + ((s*2+pl)*64 + r)*40 + c*8), src);
        }
        CPCOMMIT();
    };

    pre(0, 0);
    const int NT = SS / 32;   // 64
    for (int kt = 0; kt < NT; kt++){
        const int s = kt & 1;
        if (kt + 1 < NT){ pre(kt + 1, s ^ 1); CPWAIT(1); }
        else            { CPWAIT(0); }
        __syncthreads();

        const float* Pb  = Ps + s*128*40;
        const bf16*  Vhs = Vs + (s*2+0)*64*40;
        const bf16*  Vls = Vs + (s*2+1)*64*40;

        #pragma unroll
        for (int ks = 0; ks < 2; ks++){
            const int k0 = ks*16 + 2*t;
            uns ah[2][4], al[2][4];
            #pragma unroll
            for (int mt = 0; mt < 2; mt++){
                int r0 = (wm*32 + mt*16 + g)*40;
                int r1 = r0 + 8*40;
                float2 p00 = *(const float2*)(Pb + r0 + k0);
                float2 p10 = *(const float2*)(Pb + r1 + k0);
                float2 p01 = *(const float2*)(Pb + r0 + k0 + 8);
                float2 p11 = *(const float2*)(Pb + r1 + k0 + 8);
                bsplit2(p00.x, p00.y, ah[mt][0], al[mt][0]);
                bsplit2(p10.x, p10.y, ah[mt][1], al[mt][1]);
                bsplit2(p01.x, p01.y, ah[mt][2], al[mt][2]);
                bsplit2(p11.x, p11.y, ah[mt][3], al[mt][3]);
            }
            uns bhf[4][2], blf[4][2];
            #pragma unroll
            for (int nt = 0; nt < 4; nt++){
                int rn = (wn*32 + nt*8 + g)*40;
                bhf[nt][0] = *(const uns*)(Vhs + rn + k0);
                bhf[nt][1] = *(const uns*)(Vhs + rn + k0 + 8);
                blf[nt][0] = *(const uns*)(Vls + rn + k0);
                blf[nt][1] = *(const uns*)(Vls + rn + k0 + 8);
            }
            #pragma unroll
            for (int mt = 0; mt < 2; mt++)
                #pragma unroll
                for (int nt = 0; nt < 4; nt++)
                    mma3b(acc[mt][nt], ah[mt], al[mt], bhf[nt], blf[nt]);
        }
        __syncthreads();
    }

    const int b = bh >> 4, h = bh & 15;
    #pragma unroll
    for (int mt = 0; mt < 2; mt++){
        #pragma unroll
        for (int nt = 0; nt < 4; nt++){
            const int r0 = q0 + wm*32 + mt*16 + g;
            const int r1 = r0 + 8;
            const int cb = h*64 + wn*32 + nt*8 + 2*t;
            float* a = acc[mt][nt];
            #pragma unroll
            for (int e = 0; e < 4; e++){
                int m = b*SS + ((e < 2) ? r0 : r1);
                int n = cb + (e & 1);
                bf16 hh, ll; bsplit(a[e], hh, ll);
                Ch[(size_t)m*DD + n] = hh;
                Cl[(size_t)m*DD + n] = ll;
            }
        }
    }
}

// ---------------------------------------------------------------------------
extern "C" void kernel_launch(void* const* d_in, const int* in_sizes, int n_in,
                              void* d_out, int out_size)
{
    const float* q    = (const float*)d_in[0];
    const float* k    = (const float*)d_in[1];
    const float* v    = (const float*)d_in[2];
    const int*   mask = (const int*)  d_in[3];
    const float* Wq   = (const float*)d_in[4];
    const float* Wk   = (const float*)d_in[5];
    const float* Wv   = (const float*)d_in[6];
    const float* Wo   = (const float*)d_in[7];

    float* out  = (float*)d_out;               // [B,S,D]
    float* attn = out + (size_t)MM * DD;       // [B,H,S,S]

    bf16* P; cudaGetSymbolAddress((void**)&P, g_bf);
    bf16 *xa_h = P + (size_t)0*CHK, *xa_l = P + (size_t)1*CHK;
    bf16 *xb_h = P + (size_t)2*CHK, *xb_l = P + (size_t)3*CHK;
    bf16 *xc_h = P + (size_t)4*CHK, *xc_l = P + (size_t)5*CHK;
    bf16 *qh_h = P + (size_t)6*CHK, *qh_l = P + (size_t)7*CHK;
    bf16 *kh_h = P + (size_t)8*CHK, *kh_l = P + (size_t)9*CHK;
    bf16 *vt_h = P + (size_t)10*CHK, *vt_l = P + (size_t)11*CHK;
    bf16 *cx_h = P + (size_t)12*CHK, *cx_l = P + (size_t)13*CHK;
    bf16 *wb   = P + (size_t)14*CHK;
    bf16 *wq_h = wb + (size_t)0*WCH, *wq_l = wb + (size_t)1*WCH;
    bf16 *wk_h = wb + (size_t)2*WCH, *wk_l = wb + (size_t)3*WCH;
    bf16 *wv_h = wb + (size_t)4*WCH, *wv_l = wb + (size_t)5*WCH;
    bf16 *wo_h = wb + (size_t)6*WCH, *wo_l = wb + (size_t)7*WCH;

    cudaFuncSetAttribute(proj_bf16,
        cudaFuncAttributeMaxDynamicSharedMemorySize, 61440);
    cudaFuncSetAttribute(scores_softmax,
        cudaFuncAttributeMaxDynamicSharedMemorySize, SC_SMEM);
    cudaFuncSetAttribute(ctx_mma,
        cudaFuncAttributeMaxDynamicSharedMemorySize, 61440);

    // split inputs + weights into bf16 hi/lo planes
    split_kernel<<<MM*DD/1024, 256>>>(q, xa_h, xa_l);
    split_kernel<<<MM*DD/1024, 256>>>(k, xb_h, xb_l);
    split_kernel<<<MM*DD/1024, 256>>>(v, xc_h, xc_l);
    split_kernel<<<DD*DD/1024, 256>>>(Wq, wq_h, wq_l);
    split_kernel<<<DD*DD/1024, 256>>>(Wk, wk_h, wk_l);
    split_kernel<<<DD*DD/1024, 256>>>(Wv, wv_h, wv_l);
    split_kernel<<<DD*DD/1024, 256>>>(Wo, wo_h, wo_l);
    maskpack_kernel<<<SS*SS/256, 256>>>(mask);

    dim3 gproj(DD / 64, MM / 128);   // (16, 32)

    proj_bf16<<<gproj, 256, 61440>>>(xa_h, xa_l, wq_h, wq_l, nullptr, qh_h, qh_l, 1);
    proj_bf16<<<gproj, 256, 61440>>>(xb_h, xb_l, wk_h, wk_l, nullptr, kh_h, kh_l, 1);
    proj_bf16<<<gproj, 256, 61440>>>(xc_h, xc_l, wv_h, wv_l, nullptr, vt_h, vt_l, 2);

    scores_softmax<<<dim3(SS/16, BH), 256, SC_SMEM>>>(qh_h, qh_l, kh_h, kh_l, attn);

    ctx_mma<<<dim3(SS/128, BH), 256, 61440>>>(attn, vt_h, vt_l, cx_h, cx_l);

    proj_bf16<<<gproj, 256, 61440>>>(cx_h, cx_l, wo_h, wo_l, out, nullptr, nullptr, 0);
}

// round 9
// speedup vs baseline: 4.0444x; 1.2666x over previous
#include <cuda_runtime.h>
#include <cuda_fp16.h>
#include <math.h>

// Problem constants
#define BB   2
#define SS   2048
#define DD   1024
#define HH   16
#define DH   64
#define MM   (BB*SS)     // 4096
#define BH   (BB*HH)     // 32

typedef __half h16;
typedef unsigned uns;

// ---------------------------------------------------------------------------
// Scratch arena (device globals: allocation-free)
// layout (chunks of 4M halves):
// 0:xa_h 1:xb_h 2:xc_h      (activation hi planes [M,K])
// 3:qh_h                    (Q heads hi [BH,S,DH])
// 4:kh_h 5:kh_l             (K heads hi+lo [BH,S,DH])
// 6:vt_h 7:vt_l             (V transposed hi+lo [BH,DH,S])
// 8:cx_h                    (ctx hi [M,D])
// weights (1M halves each): wq_h,wq_l,wk_h,wk_l,wv_h,wv_l,wo_h,wo_l
// ---------------------------------------------------------------------------
#define CHK (1u<<22)
#define WCH (1u<<20)
__device__ h16 g_hf[(size_t)9*CHK + 8*WCH];
__device__ unsigned g_mbits[(size_t)SS*SS/32];

// ---------------------------------------------------------------------------
// helpers
// ---------------------------------------------------------------------------
__device__ __forceinline__ unsigned smem_u32(const void* p){
    unsigned r;
    asm("{ .reg .u64 t; cvta.to.shared.u64 t, %1; cvt.u32.u64 %0, t; }"
        : "=r"(r) : "l"(p));
    return r;
}
#define CP16(dst,src) asm volatile("cp.async.cg.shared.global [%0], [%1], 16;\n" :: "r"(dst), "l"(src))
#define CPCOMMIT()    asm volatile("cp.async.commit_group;\n")
#define CPWAIT(N)     asm volatile("cp.async.wait_group %0;\n" :: "n"(N))

__device__ __forceinline__ uns pkf(float a, float b){   // pack 2 floats -> half2
    __half2 t = __floats2half2_rn(a, b);
    return *(uns*)&t;
}
__device__ __forceinline__ uns pkh(h16 a, h16 b){
    return (uns)__half_as_ushort(a) | ((uns)__half_as_ushort(b) << 16);
}
__device__ __forceinline__ void hsplit(float x, h16 &h, h16 &l){
    h = __float2half_rn(x);
    l = __float2half_rn(x - __half2float(h));
}

__device__ __forceinline__ void mma_f16(float c[4], const uns a[4], const uns b[2]){
    asm volatile("mma.sync.aligned.m16n8k16.row.col.f32.f16.f16.f32 "
        "{%0,%1,%2,%3}, {%4,%5,%6,%7}, {%8,%9}, {%0,%1,%2,%3};"
        : "+f"(c[0]),"+f"(c[1]),"+f"(c[2]),"+f"(c[3])
        : "r"(a[0]),"r"(a[1]),"r"(a[2]),"r"(a[3]),"r"(b[0]),"r"(b[1]));
}
// one-sided compensated: c += Ah*Bh + Ah*Bl
__device__ __forceinline__ void mma2(float c[4], const uns ah[4],
                                     const uns bh[2], const uns bl[2]){
    mma_f16(c, ah, bh);
    mma_f16(c, ah, bl);
}

// ---------------------------------------------------------------------------
// fp32 -> fp16 planes
// ---------------------------------------------------------------------------
__global__ __launch_bounds__(256) void split1(
    const float* __restrict__ x, h16* __restrict__ hi)
{
    int i = (blockIdx.x * 256 + threadIdx.x) * 4;
    float4 v = *(const float4*)(x + i);
    *(uint2*)(hi + i) = make_uint2(pkf(v.x, v.y), pkf(v.z, v.w));
}
__global__ __launch_bounds__(256) void split2(
    const float* __restrict__ x, h16* __restrict__ hi, h16* __restrict__ lo)
{
    int i = (blockIdx.x * 256 + threadIdx.x) * 4;
    float4 v = *(const float4*)(x + i);
    h16 h0,l0,h1,l1,h2,l2,h3,l3;
    hsplit(v.x,h0,l0); hsplit(v.y,h1,l1); hsplit(v.z,h2,l2); hsplit(v.w,h3,l3);
    *(uint2*)(hi + i) = make_uint2(pkh(h0,h1), pkh(h2,h3));
    *(uint2*)(lo + i) = make_uint2(pkh(l0,l1), pkh(l2,l3));
}

__global__ __launch_bounds__(256) void maskpack_kernel(const int* __restrict__ mask)
{
    int i = blockIdx.x * 256 + threadIdx.x;
    unsigned w = __ballot_sync(0xffffffffu, mask[i] != 0);
    if ((threadIdx.x & 31) == 0) g_mbits[i >> 5] = w;
}

// ---------------------------------------------------------------------------
// C = A[M,K] @ W[N,K]^T, fp16 one-sided compensated (W has hi+lo planes).
// CTA 128(M) x 64(N), k-tile 32, 256 thr = 8 warps (4m x 2n), warp 32x32.
// mode 0: fp32 flat [M,DD]
// mode 1: hi-only   [BH,S,DH]   (Q)
// mode 2: hi+lo     [BH,S,DH]   (K)
// mode 3: hi+lo transposed [BH,DH,S]  (V)
// static smem: As[2][128][40] + Ws[2][2][64][40] halves = 40960 B
// ---------------------------------------------------------------------------
__global__ __launch_bounds__(256) void proj_mma(
    const h16* __restrict__ Ah_g,
    const h16* __restrict__ Wh_g, const h16* __restrict__ Wl_g,
    float* __restrict__ Cf, h16* __restrict__ Ch, h16* __restrict__ Cl,
    int mode)
{
    __shared__ h16 As[2][128][40];
    __shared__ h16 Ws[2][2][64][40];   // [pl][stage]

    const int tid = threadIdx.x, lane = tid & 31, wid = tid >> 5;
    const int wm = wid >> 1, wn = wid & 1;
    const int g = lane >> 2, t = lane & 3;
    const int m0 = blockIdx.y * 128, n0 = blockIdx.x * 64;

    float acc[2][4][4];
    #pragma unroll
    for (int i=0;i<2;i++)
        #pragma unroll
        for (int j=0;j<4;j++)
            #pragma unroll
            for (int e=0;e<4;e++) acc[i][j][e]=0.f;

    auto pre = [&](int kt, int s){
        const int k0 = kt * 32;
        #pragma unroll
        for (int i = 0; i < 2; i++){               // A: 512 chunks
            int idx = tid + i*256;
            int r = idx >> 2, c = idx & 3;
            CP16(smem_u32(&As[s][r][c*8]), Ah_g + (size_t)(m0+r)*DD + k0 + c*8);
        }
        #pragma unroll
        for (int i = 0; i < 2; i++){               // W: 512 chunks (2 planes)
            int idx = tid + i*256;
            int pl = idx >> 8, rem = idx & 255;
            int r = rem >> 2, c = rem & 3;
            CP16(smem_u32(&Ws[pl][s][r][c*8]),
                 (pl ? Wl_g : Wh_g) + (size_t)(n0+r)*DD + k0 + c*8);
        }
        CPCOMMIT();
    };

    pre(0, 0);
    const int NT = DD / 32;   // 32
    for (int kt = 0; kt < NT; kt++){
        const int s = kt & 1;
        if (kt + 1 < NT){ pre(kt + 1, s ^ 1); CPWAIT(1); }
        else            { CPWAIT(0); }
        __syncthreads();

        #pragma unroll
        for (int ks = 0; ks < 2; ks++){
            const int k0 = ks*16 + 2*t;
            uns ah[2][4];
            #pragma unroll
            for (int mt = 0; mt < 2; mt++){
                const int mb = wm*32 + mt*16;
                ah[mt][0] = *(const uns*)&As[s][mb + g    ][k0];
                ah[mt][1] = *(const uns*)&As[s][mb + 8 + g][k0];
                ah[mt][2] = *(const uns*)&As[s][mb + g    ][k0 + 8];
                ah[mt][3] = *(const uns*)&As[s][mb + 8 + g][k0 + 8];
            }
            uns bh[4][2], bl[4][2];
            #pragma unroll
            for (int nt = 0; nt < 4; nt++){
                const int nb = wn*32 + nt*8 + g;
                bh[nt][0] = *(const uns*)&Ws[0][s][nb][k0];
                bh[nt][1] = *(const uns*)&Ws[0][s][nb][k0 + 8];
                bl[nt][0] = *(const uns*)&Ws[1][s][nb][k0];
                bl[nt][1] = *(const uns*)&Ws[1][s][nb][k0 + 8];
            }
            #pragma unroll
            for (int mt = 0; mt < 2; mt++)
                #pragma unroll
                for (int nt = 0; nt < 4; nt++)
                    mma2(acc[mt][nt], ah[mt], bh[nt], bl[nt]);
        }
        __syncthreads();
    }

    #pragma unroll
    for (int mt = 0; mt < 2; mt++){
        #pragma unroll
        for (int nt = 0; nt < 4; nt++){
            const int r0 = m0 + wm*32 + mt*16 + g;
            const int r1 = r0 + 8;
            const int cb = n0 + wn*32 + nt*8 + 2*t;
            float* a = acc[mt][nt];
            if (mode == 0){
                *(float2*)&Cf[(size_t)r0*DD + cb] = make_float2(a[0], a[1]);
                *(float2*)&Cf[(size_t)r1*DD + cb] = make_float2(a[2], a[3]);
            } else if (mode == 1 || mode == 2){
                const int h = cb >> 6, dh = cb & 63;
                #pragma unroll
                for (int p = 0; p < 2; p++){
                    int m = p ? r1 : r0;
                    int b = m >> 11, sq = m & (SS - 1);
                    size_t base = (((size_t)(b*HH + h))*SS + sq)*DH + dh;
                    float x0 = a[p*2], x1 = a[p*2+1];
                    if (mode == 1){
                        *(uns*)&Ch[base] = pkf(x0, x1);
                    } else {
                        h16 h0,l0,h1,l1;
                        hsplit(x0,h0,l0); hsplit(x1,h1,l1);
                        *(uns*)&Ch[base] = pkh(h0,h1);
                        *(uns*)&Cl[base] = pkh(l0,l1);
                    }
                }
            } else {
                #pragma unroll
                for (int e = 0; e < 4; e++){
                    int m = (e < 2) ? r0 : r1;
                    int n = cb + (e & 1);
                    int b = m >> 11, sq = m & (SS - 1);
                    int h = n >> 6, dh = n & 63;
                    size_t idx = (((size_t)(b*HH + h))*DH + dh)*SS + sq;
                    h16 hh, ll; hsplit(a[e], hh, ll);
                    Ch[idx] = hh; Cl[idx] = ll;
                }
            }
        }
    }
}

// ---------------------------------------------------------------------------
// Fused scores + mask + softmax. fp16 one-sided (K compensated, Q hi only).
// CTA = 16 q rows x 2048 keys. 256 thr, warp owns 16 keys / 128-key block.
// dyn smem: ps[16][2052]f32 + q[16][72]h + k[2buf][2pl][128][72]h + invs
// ---------------------------------------------------------------------------
#define SC_SMEM (16*2052*4 + 16*72*2 + 2*2*128*72*2 + 64)   // 207424 B

__global__ __launch_bounds__(256) void scores_softmax(
    const h16* __restrict__ Qh_g,
    const h16* __restrict__ Kh_g, const h16* __restrict__ Kl_g,
    float* __restrict__ attn)
{
    extern __shared__ __align__(16) unsigned char dynsm[];
    float* ps  = (float*)dynsm;
    h16* qsm   = (h16*)(dynsm + 16*2052*4);
    h16* ksm   = (h16*)(dynsm + 16*2052*4 + 16*72*2);
    float* invs= (float*)(dynsm + 16*2052*4 + 16*72*2 + 2*2*128*72*2);

    const int tid = threadIdx.x, lane = tid & 31, wid = tid >> 5;
    const int g = lane >> 2, t = lane & 3;
    const int bh = blockIdx.y, q0 = blockIdx.x * 16;

    // stage Q tile hi plane (16x64) - 128 chunks
    if (tid < 128){
        int r = tid >> 3, c = tid & 7;
        CP16(smem_u32(qsm + r*72 + c*8),
             Qh_g + ((size_t)bh*SS + q0 + r)*DH + c*8);
    }

    auto pre = [&](int kb, int s){
        #pragma unroll
        for (int i = 0; i < 8; i++){      // 2048 chunks (2 planes x 128 x 8)
            int idx = tid + i*256;
            int pl = idx >> 10, j = idx & 1023;
            int r = j >> 3, c = j & 7;
            const h16* src = (pl ? Kl_g : Kh_g)
                           + ((size_t)bh*SS + kb*128 + r)*DH + c*8;
            CP16(smem_u32(ksm + ((s*2+pl)*128 + r)*72 + c*8), src);
        }
        CPCOMMIT();
    };

    pre(0, 0);   // commits Q staging + K block 0 together

    uns qah[4][4];
    const int nbase = wid * 16;

    for (int kb = 0; kb < 16; kb++){
        const int s = kb & 1;
        if (kb + 1 < 16){ pre(kb + 1, s ^ 1); CPWAIT(1); }
        else            { CPWAIT(0); }
        __syncthreads();

        if (kb == 0){
            #pragma unroll
            for (int ck = 0; ck < 4; ck++){
                int k0 = ck*16 + 2*t;
                qah[ck][0] = *(const uns*)(qsm + (g    )*72 + k0);
                qah[ck][1] = *(const uns*)(qsm + (g + 8)*72 + k0);
                qah[ck][2] = *(const uns*)(qsm + (g    )*72 + k0 + 8);
                qah[ck][3] = *(const uns*)(qsm + (g + 8)*72 + k0 + 8);
            }
        }

        const h16* khs = ksm + (s*2+0)*128*72;
        const h16* kls = ksm + (s*2+1)*128*72;
        float acc[2][4] = {{0.f,0.f,0.f,0.f},{0.f,0.f,0.f,0.f}};

        #pragma unroll
        for (int ck = 0; ck < 4; ck++){
            int k0 = ck*16 + 2*t;
            uns bhf[2][2], blf[2][2];
            #pragma unroll
            for (int nt = 0; nt < 2; nt++){
                int rn = (nbase + nt*8 + g)*72;
                bhf[nt][0] = *(const uns*)(khs + rn + k0);
                bhf[nt][1] = *(const uns*)(khs + rn + k0 + 8);
                blf[nt][0] = *(const uns*)(kls + rn + k0);
                blf[nt][1] = *(const uns*)(kls + rn + k0 + 8);
            }
            mma2(acc[0], qah[ck], bhf[0], blf[0]);
            mma2(acc[1], qah[ck], bhf[1], blf[1]);
        }

        #pragma unroll
        for (int nt = 0; nt < 2; nt++){
            int col = kb*128 + nbase + nt*8 + 2*t;
            ps[(g    )*2052 + col    ] = acc[nt][0] * 0.125f;
            ps[(g    )*2052 + col + 1] = acc[nt][1] * 0.125f;
            ps[(g + 8)*2052 + col    ] = acc[nt][2] * 0.125f;
            ps[(g + 8)*2052 + col + 1] = acc[nt][3] * 0.125f;
        }
        __syncthreads();
    }

    // softmax: 16 threads per row, bit-packed mask
    const int row = tid >> 4, sub = tid & 15;
    const unsigned* mb = g_mbits + (((size_t)(q0 + row)) * SS >> 5);
    float* pr = ps + row * 2052;

    float mx = -3.0e38f;
    for (int k2 = sub; k2 < SS; k2 += 16){
        float sv = pr[k2];
        unsigned w = mb[k2 >> 5];
        if (!((w >> (k2 & 31)) & 1)) sv = -1e34f;
        pr[k2] = sv;
        mx = fmaxf(mx, sv);
    }
    #pragma unroll
    for (int off = 1; off < 16; off <<= 1)
        mx = fmaxf(mx, __shfl_xor_sync(0xffffffffu, mx, off));

    float sum = 0.f;
    for (int k2 = sub; k2 < SS; k2 += 16){
        float e = __expf(pr[k2] - mx);
        pr[k2] = e;
        sum += e;
    }
    #pragma unroll
    for (int off = 1; off < 16; off <<= 1)
        sum += __shfl_xor_sync(0xffffffffu, sum, off);

    if (sub == 0) invs[row] = 1.f / sum;
    __syncthreads();

    float* Ar = attn + ((size_t)bh * SS + q0) * SS;
    #pragma unroll
    for (int i = 0; i < 32; i++){
        int idx = tid + i * 256;
        int r = idx >> 9, c4 = idx & 511;
        float inv = invs[r];
        float4 v = *(float4*)&ps[r * 2052 + c4 * 4];
        v.x *= inv; v.y *= inv; v.z *= inv; v.w *= inv;
        *(float4*)&Ar[(size_t)r * SS + c4 * 4] = v;
    }
}

// ---------------------------------------------------------------------------
// ctx = attn(fp32) @ V. P converted fp32->fp16 hi at frag load (no lo),
// V pre-split hi+lo transposed. CTA 128(q) x 64(dh), k-tile 32.
// dyn smem: Ps[2][128][40]f32 + Vs[2pl][2][64][40]h = 61440 B
// Output: ctx hi plane only [M,DD].
// ---------------------------------------------------------------------------
__global__ __launch_bounds__(256) void ctx_mma(
    const float* __restrict__ attn,
    const h16* __restrict__ Vh_g, const h16* __restrict__ Vl_g,
    h16* __restrict__ Ch)
{
    extern __shared__ __align__(16) unsigned char dynsm[];
    float* Ps = (float*)dynsm;                 // [2][128][40]
    h16*  Vs  = (h16*)(dynsm + 2*128*40*4);    // [2pl][2][64][40]

    const int tid = threadIdx.x, lane = tid & 31, wid = tid >> 5;
    const int wm = wid >> 1, wn = wid & 1;
    const int g = lane >> 2, t = lane & 3;
    const int bh = blockIdx.y, q0 = blockIdx.x * 128;

    const float* Ab  = attn + (size_t)bh * SS * SS;
    const h16*   Vhb = Vh_g + (size_t)bh * DH * SS;
    const h16*   Vlb = Vl_g + (size_t)bh * DH * SS;

    float acc[2][4][4];
    #pragma unroll
    for (int i=0;i<2;i++)
        #pragma unroll
        for (int j=0;j<4;j++)
            #pragma unroll
            for (int e=0;e<4;e++) acc[i][j][e]=0.f;

    auto pre = [&](int kt, int s){
        const int k0 = kt * 32;
        #pragma unroll
        for (int i = 0; i < 4; i++){          // P: 1024 chunks (4 f32 each)
            int idx = tid + i*256;
            int r = idx >> 3, c = idx & 7;
            CP16(smem_u32(Ps + (s*128 + r)*40 + c*4),
                 Ab + (size_t)(q0 + r)*SS + k0 + c*4);
        }
        #pragma unroll
        for (int i = 0; i < 2; i++){          // V: 512 chunks (2 planes)
            int idx = tid + i*256;
            int pl = idx >> 8, rem = idx & 255;
            int r = rem >> 2, c = rem & 3;
            const h16* src = (pl ? Vlb : Vhb) + (size_t)r*SS + k0 + c*8;
            CP16(smem_u32(Vs + ((pl*2+s)*64 + r)*40 + c*8), src);
        }
        CPCOMMIT();
    };

    pre(0, 0);
    const int NT = SS / 32;   // 64
    for (int kt = 0; kt < NT; kt++){
        const int s = kt & 1;
        if (kt + 1 < NT){ pre(kt + 1, s ^ 1); CPWAIT(1); }
        else            { CPWAIT(0); }
        __syncthreads();

        const float* Pb  = Ps + s*128*40;
        const h16*   Vhs = Vs + (0*2+s)*64*40;
        const h16*   Vls = Vs + (1*2+s)*64*40;

        #pragma unroll
        for (int ks = 0; ks < 2; ks++){
            const int k0 = ks*16 + 2*t;
            uns ah[2][4];
            #pragma unroll
            for (int mt = 0; mt < 2; mt++){
                int r0 = (wm*32 + mt*16 + g)*40;
                int r1 = r0 + 8*40;
                float2 p00 = *(const float2*)(Pb + r0 + k0);
                float2 p10 = *(const float2*)(Pb + r1 + k0);
                float2 p01 = *(const float2*)(Pb + r0 + k0 + 8);
                float2 p11 = *(const float2*)(Pb + r1 + k0 + 8);
                ah[mt][0] = pkf(p00.x, p00.y);
                ah[mt][1] = pkf(p10.x, p10.y);
                ah[mt][2] = pkf(p01.x, p01.y);
                ah[mt][3] = pkf(p11.x, p11.y);
            }
            uns bhf[4][2], blf[4][2];
            #pragma unroll
            for (int nt = 0; nt < 4; nt++){
                int rn = (wn*32 + nt*8 + g)*40;
                bhf[nt][0] = *(const uns*)(Vhs + rn + k0);
                bhf[nt][1] = *(const uns*)(Vhs + rn + k0 + 8);
                blf[nt][0] = *(const uns*)(Vls + rn + k0);
                blf[nt][1] = *(const uns*)(Vls + rn + k0 + 8);
            }
            #pragma unroll
            for (int mt = 0; mt < 2; mt++)
                #pragma unroll
                for (int nt = 0; nt < 4; nt++)
                    mma2(acc[mt][nt], ah[mt], bhf[nt], blf[nt]);
        }
        __syncthreads();
    }

    const int b = bh >> 4, h = bh & 15;
    #pragma unroll
    for (int mt = 0; mt < 2; mt++){
        #pragma unroll
        for (int nt = 0; nt < 4; nt++){
            const int r0 = q0 + wm*32 + mt*16 + g;
            const int r1 = r0 + 8;
            const int cb = h*64 + wn*32 + nt*8 + 2*t;
            float* a = acc[mt][nt];
            *(uns*)&Ch[(size_t)(b*SS + r0)*DD + cb] = pkf(a[0], a[1]);
            *(uns*)&Ch[(size_t)(b*SS + r1)*DD + cb] = pkf(a[2], a[3]);
        }
    }
}

// ---------------------------------------------------------------------------
extern "C" void kernel_launch(void* const* d_in, const int* in_sizes, int n_in,
                              void* d_out, int out_size)
{
    const float* q    = (const float*)d_in[0];
    const float* k    = (const float*)d_in[1];
    const float* v    = (const float*)d_in[2];
    const int*   mask = (const int*)  d_in[3];
    const float* Wq   = (const float*)d_in[4];
    const float* Wk   = (const float*)d_in[5];
    const float* Wv   = (const float*)d_in[6];
    const float* Wo   = (const float*)d_in[7];

    float* out  = (float*)d_out;               // [B,S,D]
    float* attn = out + (size_t)MM * DD;       // [B,H,S,S]

    h16* P; cudaGetSymbolAddress((void**)&P, g_hf);
    h16 *xa_h = P + (size_t)0*CHK;
    h16 *xb_h = P + (size_t)1*CHK;
    h16 *xc_h = P + (size_t)2*CHK;
    h16 *qh_h = P + (size_t)3*CHK;
    h16 *kh_h = P + (size_t)4*CHK, *kh_l = P + (size_t)5*CHK;
    h16 *vt_h = P + (size_t)6*CHK, *vt_l = P + (size_t)7*CHK;
    h16 *cx_h = P + (size_t)8*CHK;
    h16 *wb   = P + (size_t)9*CHK;
    h16 *wq_h = wb + (size_t)0*WCH, *wq_l = wb + (size_t)1*WCH;
    h16 *wk_h = wb + (size_t)2*WCH, *wk_l = wb + (size_t)3*WCH;
    h16 *wv_h = wb + (size_t)4*WCH, *wv_l = wb + (size_t)5*WCH;
    h16 *wo_h = wb + (size_t)6*WCH, *wo_l = wb + (size_t)7*WCH;

    cudaFuncSetAttribute(scores_softmax,
        cudaFuncAttributeMaxDynamicSharedMemorySize, SC_SMEM);
    cudaFuncSetAttribute(ctx_mma,
        cudaFuncAttributeMaxDynamicSharedMemorySize, 61440);

    // activations: hi-plane only; weights: hi+lo
    split1<<<MM*DD/1024, 256>>>(q, xa_h);
    split1<<<MM*DD/1024, 256>>>(k, xb_h);
    split1<<<MM*DD/1024, 256>>>(v, xc_h);
    split2<<<DD*DD/1024, 256>>>(Wq, wq_h, wq_l);
    split2<<<DD*DD/1024, 256>>>(Wk, wk_h, wk_l);
    split2<<<DD*DD/1024, 256>>>(Wv, wv_h, wv_l);
    split2<<<DD*DD/1024, 256>>>(Wo, wo_h, wo_l);
    maskpack_kernel<<<SS*SS/256, 256>>>(mask);

    dim3 gproj(DD / 64, MM / 128);   // (16, 32)

    proj_mma<<<gproj, 256>>>(xa_h, wq_h, wq_l, nullptr, qh_h, nullptr, 1);
    proj_mma<<<gproj, 256>>>(xb_h, wk_h, wk_l, nullptr, kh_h, kh_l,   2);
    proj_mma<<<gproj, 256>>>(xc_h, wv_h, wv_l, nullptr, vt_h, vt_l,   3);

    scores_softmax<<<dim3(SS/16, BH), 256, SC_SMEM>>>(qh_h, kh_h, kh_l, attn);

    ctx_mma<<<dim3(SS/128, BH), 256, 61440>>>(attn, vt_h, vt_l, cx_h);

    proj_mma<<<gproj, 256>>>(cx_h, wo_h, wo_l, out, nullptr, nullptr, 0);
}

// round 11
// speedup vs baseline: 4.1644x; 1.0297x over previous
#include <cuda_runtime.h>
#include <cuda_fp16.h>
#include <math.h>

// Problem constants
#define BB   2
#define SS   2048
#define DD   1024
#define HH   16
#define DH   64
#define MM   (BB*SS)     // 4096
#define BH   (BB*HH)     // 32

typedef __half h16;
typedef unsigned uns;

// ---------------------------------------------------------------------------
// Scratch arena (device globals: allocation-free)
// ---------------------------------------------------------------------------
#define CHK (1u<<22)
#define WCH (1u<<20)
__device__ h16 g_hf[(size_t)9*CHK + 8*WCH];
__device__ h16 g_p16[(size_t)BH*SS*SS];          // fp16 probabilities
__device__ unsigned g_mbits[(size_t)SS*SS/32];

// ---------------------------------------------------------------------------
// helpers
// ---------------------------------------------------------------------------
__device__ __forceinline__ unsigned smem_u32(const void* p){
    unsigned r;
    asm("{ .reg .u64 t; cvta.to.shared.u64 t, %1; cvt.u32.u64 %0, t; }"
        : "=r"(r) : "l"(p));
    return r;
}
#define CP16(dst,src) asm volatile("cp.async.cg.shared.global [%0], [%1], 16;\n" :: "r"(dst), "l"(src))
#define CPCOMMIT()    asm volatile("cp.async.commit_group;\n")
#define CPWAIT(N)     asm volatile("cp.async.wait_group %0;\n" :: "n"(N))

__device__ __forceinline__ uns pkf(float a, float b){
    __half2 t = __floats2half2_rn(a, b);
    return *(uns*)&t;
}
__device__ __forceinline__ uns pkh(h16 a, h16 b){
    return (uns)__half_as_ushort(a) | ((uns)__half_as_ushort(b) << 16);
}
__device__ __forceinline__ void hsplit(float x, h16 &h, h16 &l){
    h = __float2half_rn(x);
    l = __float2half_rn(x - __half2float(h));
}

__device__ __forceinline__ void mma_f16(float c[4], const uns a[4], const uns b0, const uns b1){
    asm volatile("mma.sync.aligned.m16n8k16.row.col.f32.f16.f16.f32 "
        "{%0,%1,%2,%3}, {%4,%5,%6,%7}, {%8,%9}, {%0,%1,%2,%3};"
        : "+f"(c[0]),"+f"(c[1]),"+f"(c[2]),"+f"(c[3])
        : "r"(a[0]),"r"(a[1]),"r"(a[2]),"r"(a[3]),"r"(b0),"r"(b1));
}
__device__ __forceinline__ void ldm4(uns r[4], uns addr){
    asm volatile("ldmatrix.sync.aligned.m8n8.x4.shared.b16 {%0,%1,%2,%3}, [%4];"
        : "=r"(r[0]),"=r"(r[1]),"=r"(r[2]),"=r"(r[3]) : "r"(addr));
}
// A-map lane offsets: r0=rows[0:8)k0, r1=rows[8:16)k0, r2=rows[0:8)k8, r3=rows[8:16)k8
#define AROW(lane) (((lane)&7) + (((lane)>>3)&1)*8)
#define ACOL(lane) (((lane)>>4)*8)
// B-map lane offsets: r0=rows[0:8)k0, r1=rows[0:8)k8, r2=rows[8:16)k0, r3=rows[8:16)k8
#define BROW(lane) (((lane)&7) + (((lane)>>4)&1)*8)
#define BCOL(lane) ((((lane)>>3)&1)*8)

// ---------------------------------------------------------------------------
// fp32 -> fp16 planes
// ---------------------------------------------------------------------------
__global__ __launch_bounds__(256) void split1(
    const float* __restrict__ x, h16* __restrict__ hi)
{
    int i = (blockIdx.x * 256 + threadIdx.x) * 4;
    float4 v = *(const float4*)(x + i);
    *(uint2*)(hi + i) = make_uint2(pkf(v.x, v.y), pkf(v.z, v.w));
}
__global__ __launch_bounds__(256) void split2k(
    const float* __restrict__ x, h16* __restrict__ hi, h16* __restrict__ lo)
{
    int i = (blockIdx.x * 256 + threadIdx.x) * 4;
    float4 v = *(const float4*)(x + i);
    h16 h0,l0,h1,l1,h2,l2,h3,l3;
    hsplit(v.x,h0,l0); hsplit(v.y,h1,l1); hsplit(v.z,h2,l2); hsplit(v.w,h3,l3);
    *(uint2*)(hi + i) = make_uint2(pkh(h0,h1), pkh(h2,h3));
    *(uint2*)(lo + i) = make_uint2(pkh(l0,l1), pkh(l2,l3));
}

__global__ __launch_bounds__(256) void maskpack_kernel(const int* __restrict__ mask)
{
    int i = blockIdx.x * 256 + threadIdx.x;
    unsigned w = __ballot_sync(0xffffffffu, mask[i] != 0);
    if ((threadIdx.x & 31) == 0) g_mbits[i >> 5] = w;
}

// ---------------------------------------------------------------------------
// C = A[M,K] @ W[N,K]^T, fp16 one-sided compensated. ldmatrix frag loads.
// CTA 128(M) x 64(N), k-tile 32, 256 thr = 8 warps (4m x 2n), warp 32x32.
// mode 0: fp32 flat  1: hi-only [BH,S,DH]  2: hi+lo [BH,S,DH]  3: hi+lo T [BH,DH,S]
// ---------------------------------------------------------------------------
__global__ __launch_bounds__(256) void proj_mma(
    const h16* __restrict__ Ah_g,
    const h16* __restrict__ Wh_g, const h16* __restrict__ Wl_g,
    float* __restrict__ Cf, h16* __restrict__ Ch, h16* __restrict__ Cl,
    int mode)
{
    __shared__ h16 As[2][128][40];
    __shared__ h16 Ws[2][2][64][40];   // [pl][stage]

    const int tid = threadIdx.x, lane = tid & 31, wid = tid >> 5;
    const int wm = wid >> 1, wn = wid & 1;
    const int g = lane >> 2, t = lane & 3;
    const int m0 = blockIdx.y * 128, n0 = blockIdx.x * 64;

    const uns as_a = smem_u32(&As[0][0][0]);
    const uns ws_a = smem_u32(&Ws[0][0][0][0]);
    const int arow = AROW(lane), acol = ACOL(lane);
    const int brow = BROW(lane), bcol = BCOL(lane);

    float acc[2][4][4];
    #pragma unroll
    for (int i=0;i<2;i++)
        #pragma unroll
        for (int j=0;j<4;j++)
            #pragma unroll
            for (int e=0;e<4;e++) acc[i][j][e]=0.f;

    auto pre = [&](int kt, int s){
        const int k0 = kt * 32;
        #pragma unroll
        for (int i = 0; i < 2; i++){               // A: 512 chunks (128r x 4c)
            int idx = tid + i*256;
            int r = idx >> 2, c = idx & 3;
            CP16(smem_u32(&As[s][r][c*8]), Ah_g + (size_t)(m0+r)*DD + k0 + c*8);
        }
        #pragma unroll
        for (int i = 0; i < 2; i++){               // W: 512 chunks (2pl x 64r x 4c)
            int idx = tid + i*256;
            int pl = idx >> 8, rem = idx & 255;
            int r = rem >> 2, c = rem & 3;
            CP16(smem_u32(&Ws[pl][s][r][c*8]),
                 (pl ? Wl_g : Wh_g) + (size_t)(n0+r)*DD + k0 + c*8);
        }
        CPCOMMIT();
    };

    pre(0, 0);
    const int NT = DD / 32;   // 32
    for (int kt = 0; kt < NT; kt++){
        const int s = kt & 1;
        if (kt + 1 < NT){ pre(kt + 1, s ^ 1); CPWAIT(1); }
        else            { CPWAIT(0); }
        __syncthreads();

        #pragma unroll
        for (int ks = 0; ks < 2; ks++){
            const int k0 = ks*16;
            uns ah[2][4];
            #pragma unroll
            for (int mt = 0; mt < 2; mt++)
                ldm4(ah[mt], as_a + ((s*128 + wm*32 + mt*16 + arow)*40
                                     + k0 + acol)*2);
            uns bhq[2][4], blq[2][4];
            #pragma unroll
            for (int hq = 0; hq < 2; hq++){
                ldm4(bhq[hq], ws_a + (((0*2+s)*64 + wn*32 + hq*16 + brow)*40
                                      + k0 + bcol)*2);
                ldm4(blq[hq], ws_a + (((1*2+s)*64 + wn*32 + hq*16 + brow)*40
                                      + k0 + bcol)*2);
            }
            #pragma unroll
            for (int mt = 0; mt < 2; mt++)
                #pragma unroll
                for (int nt = 0; nt < 4; nt++){
                    const int hq = nt >> 1, p = (nt & 1) * 2;
                    mma_f16(acc[mt][nt], ah[mt], bhq[hq][p], bhq[hq][p+1]);
                    mma_f16(acc[mt][nt], ah[mt], blq[hq][p], blq[hq][p+1]);
                }
        }
        __syncthreads();
    }

    #pragma unroll
    for (int mt = 0; mt < 2; mt++){
        #pragma unroll
        for (int nt = 0; nt < 4; nt++){
            const int r0 = m0 + wm*32 + mt*16 + g;
            const int r1 = r0 + 8;
            const int cb = n0 + wn*32 + nt*8 + 2*t;
            float* a = acc[mt][nt];
            if (mode == 0){
                *(float2*)&Cf[(size_t)r0*DD + cb] = make_float2(a[0], a[1]);
                *(float2*)&Cf[(size_t)r1*DD + cb] = make_float2(a[2], a[3]);
            } else if (mode == 1 || mode == 2){
                const int h = cb >> 6, dh = cb & 63;
                #pragma unroll
                for (int p = 0; p < 2; p++){
                    int m = p ? r1 : r0;
                    int b = m >> 11, sq = m & (SS - 1);
                    size_t base = (((size_t)(b*HH + h))*SS + sq)*DH + dh;
                    float x0 = a[p*2], x1 = a[p*2+1];
                    if (mode == 1){
                        *(uns*)&Ch[base] = pkf(x0, x1);
                    } else {
                        h16 h0,l0,h1,l1;
                        hsplit(x0,h0,l0); hsplit(x1,h1,l1);
                        *(uns*)&Ch[base] = pkh(h0,h1);
                        *(uns*)&Cl[base] = pkh(l0,l1);
                    }
                }
            } else {
                #pragma unroll
                for (int e = 0; e < 4; e++){
                    int m = (e < 2) ? r0 : r1;
                    int n = cb + (e & 1);
                    int b = m >> 11, sq = m & (SS - 1);
                    int h = n >> 6, dh = n & 63;
                    size_t idx = (((size_t)(b*HH + h))*DH + dh)*SS + sq;
                    h16 hh, ll; hsplit(a[e], hh, ll);
                    Ch[idx] = hh; Cl[idx] = ll;
                }
            }
        }
    }
}

// ---------------------------------------------------------------------------
// Fused scores + mask + softmax. Mask+row-max folded into MMA epilogue.
// Emits attn (fp32, output) and p16 (fp16 copy for ctx).
// ---------------------------------------------------------------------------
#define SC_SMEM (16*2052*4 + 16*72*2 + 2*2*128*72*2 + 64 + 512)

__global__ __launch_bounds__(256) void scores_softmax(
    const h16* __restrict__ Qh_g,
    const h16* __restrict__ Kh_g, const h16* __restrict__ Kl_g,
    float* __restrict__ attn, h16* __restrict__ p16)
{
    extern __shared__ __align__(16) unsigned char dynsm[];
    float* ps  = (float*)dynsm;
    h16* qsm   = (h16*)(dynsm + 16*2052*4);
    h16* ksm   = (h16*)(dynsm + 16*2052*4 + 16*72*2);
    float* invs= (float*)(dynsm + 16*2052*4 + 16*72*2 + 2*2*128*72*2);
    float* wmax= invs + 16;                       // [16][8]

    const int tid = threadIdx.x, lane = tid & 31, wid = tid >> 5;
    const int g = lane >> 2, t = lane & 3;
    const int bh = blockIdx.y, q0 = blockIdx.x * 16;

    const uns q_a = smem_u32(qsm);
    const uns k_a = smem_u32(ksm);
    const int arow = AROW(lane), acol = ACOL(lane);
    const int brow = BROW(lane), bcol = BCOL(lane);

    // stage Q tile hi plane (16x64): 128 chunks
    if (tid < 128){
        int r = tid >> 3, c = tid & 7;
        CP16(smem_u32(qsm + r*72 + c*8),
             Qh_g + ((size_t)bh*SS + q0 + r)*DH + c*8);
    }

    auto pre = [&](int kb, int s){
        #pragma unroll
        for (int i = 0; i < 8; i++){     // 2048 chunks (2pl x 128r x 8c)
            int idx = tid + i*256;
            int pl = idx >> 10, j = idx & 1023;
            int r = j >> 3, c = j & 7;
            const h16* src = (pl ? Kl_g : Kh_g)
                           + ((size_t)bh*SS + kb*128 + r)*DH + c*8;
            CP16(smem_u32(ksm + ((s*2+pl)*128 + r)*72 + c*8), src);
        }
        CPCOMMIT();
    };

    pre(0, 0);

    uns qa[4][4];
    const int nbase = wid * 16;
    float mr0 = -3.0e38f, mr8 = -3.0e38f;

    for (int kb = 0; kb < 16; kb++){
        const int s = kb & 1;
        if (kb + 1 < 16){ pre(kb + 1, s ^ 1); CPWAIT(1); }
        else            { CPWAIT(0); }
        __syncthreads();

        if (kb == 0){
            #pragma unroll
            for (int ck = 0; ck < 4; ck++)
                ldm4(qa[ck], q_a + (arow*72 + ck*16 + acol)*2);
        }

        float acc[2][4] = {{0.f,0.f,0.f,0.f},{0.f,0.f,0.f,0.f}};
        #pragma unroll
        for (int ck = 0; ck < 4; ck++){
            uns bh2[4], bl2[4];
            ldm4(bh2, k_a + (((s*2+0)*128 + nbase + brow)*72 + ck*16 + bcol)*2);
            ldm4(bl2, k_a + (((s*2+1)*128 + nbase + brow)*72 + ck*16 + bcol)*2);
            mma_f16(acc[0], qa[ck], bh2[0], bh2[1]);
            mma_f16(acc[0], qa[ck], bl2[0], bl2[1]);
            mma_f16(acc[1], qa[ck], bh2[2], bh2[3]);
            mma_f16(acc[1], qa[ck], bl2[2], bl2[3]);
        }

        #pragma unroll
        for (int nt = 0; nt < 2; nt++){
            const int col = kb*128 + nbase + nt*8 + 2*t;
            const unsigned w0 = g_mbits[((size_t)(q0 + g    )*SS + col) >> 5];
            const unsigned w8 = g_mbits[((size_t)(q0 + g + 8)*SS + col) >> 5];
            const int sh = col & 31;
            float s0 = ((w0 >> sh)     & 1) ? acc[nt][0]*0.125f : -1e34f;
            float s1 = ((w0 >> (sh+1)) & 1) ? acc[nt][1]*0.125f : -1e34f;
            float s2 = ((w8 >> sh)     & 1) ? acc[nt][2]*0.125f : -1e34f;
            float s3 = ((w8 >> (sh+1)) & 1) ? acc[nt][3]*0.125f : -1e34f;
            ps[(g    )*2052 + col    ] = s0;
            ps[(g    )*2052 + col + 1] = s1;
            ps[(g + 8)*2052 + col    ] = s2;
            ps[(g + 8)*2052 + col + 1] = s3;
            mr0 = fmaxf(mr0, fmaxf(s0, s1));
            mr8 = fmaxf(mr8, fmaxf(s2, s3));
        }
        __syncthreads();
    }

    #pragma unroll
    for (int off = 1; off < 4; off <<= 1){
        mr0 = fmaxf(mr0, __shfl_xor_sync(0xffffffffu, mr0, off));
        mr8 = fmaxf(mr8, __shfl_xor_sync(0xffffffffu, mr8, off));
    }
    if (t == 0){
        wmax[(g    )*8 + wid] = mr0;
        wmax[(g + 8)*8 + wid] = mr8;
    }
    __syncthreads();

    const int row = tid >> 4, sub = tid & 15;
    float* pr = ps + row * 2052;

    float mx = -3.0e38f;
    #pragma unroll
    for (int j = 0; j < 8; j++) mx = fmaxf(mx, wmax[row*8 + j]);

    float sum = 0.f;
    for (int k2 = sub; k2 < SS; k2 += 16){
        float e = __expf(pr[k2] - mx);
        pr[k2] = e;
        sum += e;
    }
    #pragma unroll
    for (int off = 1; off < 16; off <<= 1)
        sum += __shfl_xor_sync(0xffffffffu, sum, off);

    if (sub == 0) invs[row] = 1.f / sum;
    __syncthreads();

    float* Ar = attn + ((size_t)bh * SS + q0) * SS;
    h16*   Pr = p16  + ((size_t)bh * SS + q0) * SS;
    #pragma unroll
    for (int i = 0; i < 32; i++){
        int idx = tid + i * 256;
        int r = idx >> 9, c4 = idx & 511;
        float inv = invs[r];
        float4 v = *(float4*)&ps[r * 2052 + c4 * 4];
        v.x *= inv; v.y *= inv; v.z *= inv; v.w *= inv;
        *(float4*)&Ar[(size_t)r * SS + c4 * 4] = v;
        *(uint2*)&Pr[(size_t)r * SS + c4 * 4] = make_uint2(pkf(v.x, v.y),
                                                           pkf(v.z, v.w));
    }
}

// ---------------------------------------------------------------------------
// ctx = P16 @ V (fp16 one-sided: V hi+lo). ldmatrix frags, k-tile 64 keys.
// dyn smem: Ps[2][128][72]h + Vs[2pl][2][64][72]h = 73728 B
// ---------------------------------------------------------------------------
#define CTX_SMEM (2*128*72*2 + 2*2*64*72*2)

__global__ __launch_bounds__(256) void ctx_mma(
    const h16* __restrict__ P16,
    const h16* __restrict__ Vh_g, const h16* __restrict__ Vl_g,
    h16* __restrict__ Ch)
{
    extern __shared__ __align__(16) unsigned char dynsm[];
    h16* Psm = (h16*)dynsm;                    // [2][128][72]
    h16* Vsm = (h16*)(dynsm + 2*128*72*2);     // [2pl][2][64][72]

    const int tid = threadIdx.x, lane = tid & 31, wid = tid >> 5;
    const int wm = wid >> 1, wn = wid & 1;
    const int g = lane >> 2, t = lane & 3;
    const int bh = blockIdx.y, q0 = blockIdx.x * 128;

    const uns p_a = smem_u32(Psm);
    const uns v_a = smem_u32(Vsm);
    const int arow = AROW(lane), acol = ACOL(lane);
    const int brow = BROW(lane), bcol = BCOL(lane);

    const h16* Pb  = P16  + (size_t)bh * SS * SS;
    const h16* Vhb = Vh_g + (size_t)bh * DH * SS;
    const h16* Vlb = Vl_g + (size_t)bh * DH * SS;

    float acc[2][4][4];
    #pragma unroll
    for (int i=0;i<2;i++)
        #pragma unroll
        for (int j=0;j<4;j++)
            #pragma unroll
            for (int e=0;e<4;e++) acc[i][j][e]=0.f;

    auto pre = [&](int kt, int s){
        const int k0 = kt * 64;
        #pragma unroll
        for (int i = 0; i < 4; i++){           // P: 1024 chunks (128r x 8c)
            int idx = tid + i*256;
            int r = idx >> 3, c = idx & 7;
            CP16(smem_u32(Psm + (s*128 + r)*72 + c*8),
                 Pb + (size_t)(q0 + r)*SS + k0 + c*8);
        }
        #pragma unroll
        for (int i = 0; i < 4; i++){           // V: 1024 chunks (2pl x 64r x 8c)
            int idx = tid + i*256;
            int pl = idx >> 9, rem = idx & 511;
            int r = rem >> 3, c = rem & 7;
            const h16* src = (pl ? Vlb : Vhb) + (size_t)r*SS + k0 + c*8;
            CP16(smem_u32(Vsm + ((pl*2+s)*64 + r)*72 + c*8), src);
        }
        CPCOMMIT();
    };

    pre(0, 0);
    const int NT = SS / 64;   // 32
    for (int kt = 0; kt < NT; kt++){
        const int s = kt & 1;
        if (kt + 1 < NT){ pre(kt + 1, s ^ 1); CPWAIT(1); }
        else            { CPWAIT(0); }
        __syncthreads();

        #pragma unroll
        for (int ks = 0; ks < 4; ks++){
            const int k0 = ks*16;
            uns ah[2][4];
            #pragma unroll
            for (int mt = 0; mt < 2; mt++)
                ldm4(ah[mt], p_a + ((s*128 + wm*32 + mt*16 + arow)*72
                                    + k0 + acol)*2);
            uns bhq[2][4], blq[2][4];
            #pragma unroll
            for (int hq = 0; hq < 2; hq++){
                ldm4(bhq[hq], v_a + (((0*2+s)*64 + wn*32 + hq*16 + brow)*72
                                     + k0 + bcol)*2);
                ldm4(blq[hq], v_a + (((1*2+s)*64 + wn*32 + hq*16 + brow)*72
                                     + k0 + bcol)*2);
            }
            #pragma unroll
            for (int mt = 0; mt < 2; mt++)
                #pragma unroll
                for (int nt = 0; nt < 4; nt++){
                    const int hq = nt >> 1, p = (nt & 1) * 2;
                    mma_f16(acc[mt][nt], ah[mt], bhq[hq][p], bhq[hq][p+1]);
                    mma_f16(acc[mt][nt], ah[mt], blq[hq][p], blq[hq][p+1]);
                }
        }
        __syncthreads();
    }

    const int b = bh >> 4, h = bh & 15;
    #pragma unroll
    for (int mt = 0; mt < 2; mt++){
        #pragma unroll
        for (int nt = 0; nt < 4; nt++){
            const int r0 = q0 + wm*32 + mt*16 + g;
            const int r1 = r0 + 8;
            const int cb = h*64 + wn*32 + nt*8 + 2*t;
            float* a = acc[mt][nt];
            *(uns*)&Ch[(size_t)(b*SS + r0)*DD + cb] = pkf(a[0], a[1]);
            *(uns*)&Ch[(size_t)(b*SS + r1)*DD + cb] = pkf(a[2], a[3]);
        }
    }
}

// ---------------------------------------------------------------------------
extern "C" void kernel_launch(void* const* d_in, const int* in_sizes, int n_in,
                              void* d_out, int out_size)
{
    const float* q    = (const float*)d_in[0];
    const float* k    = (const float*)d_in[1];
    const float* v    = (const float*)d_in[2];
    const int*   mask = (const int*)  d_in[3];
    const float* Wq   = (const float*)d_in[4];
    const float* Wk   = (const float*)d_in[5];
    const float* Wv   = (const float*)d_in[6];
    const float* Wo   = (const float*)d_in[7];

    float* out  = (float*)d_out;               // [B,S,D]
    float* attn = out + (size_t)MM * DD;       // [B,H,S,S]

    h16* P; cudaGetSymbolAddress((void**)&P, g_hf);
    h16* p16; cudaGetSymbolAddress((void**)&p16, g_p16);
    h16 *xa_h = P + (size_t)0*CHK;
    h16 *xb_h = P + (size_t)1*CHK;
    h16 *xc_h = P + (size_t)2*CHK;
    h16 *qh_h = P + (size_t)3*CHK;
    h16 *kh_h = P + (size_t)4*CHK, *kh_l = P + (size_t)5*CHK;
    h16 *vt_h = P + (size_t)6*CHK, *vt_l = P + (size_t)7*CHK;
    h16 *cx_h = P + (size_t)8*CHK;
    h16 *wb   = P + (size_t)9*CHK;
    h16 *wq_h = wb + (size_t)0*WCH, *wq_l = wb + (size_t)1*WCH;
    h16 *wk_h = wb + (size_t)2*WCH, *wk_l = wb + (size_t)3*WCH;
    h16 *wv_h = wb + (size_t)4*WCH, *wv_l = wb + (size_t)5*WCH;
    h16 *wo_h = wb + (size_t)6*WCH, *wo_l = wb + (size_t)7*WCH;

    cudaFuncSetAttribute(scores_softmax,
        cudaFuncAttributeMaxDynamicSharedMemorySize, SC_SMEM);
    cudaFuncSetAttribute(ctx_mma,
        cudaFuncAttributeMaxDynamicSharedMemorySize, CTX_SMEM);

    split1<<<MM*DD/1024, 256>>>(q, xa_h);
    split1<<<MM*DD/1024, 256>>>(k, xb_h);
    split1<<<MM*DD/1024, 256>>>(v, xc_h);
    split2k<<<DD*DD/1024, 256>>>(Wq, wq_h, wq_l);
    split2k<<<DD*DD/1024, 256>>>(Wk, wk_h, wk_l);
    split2k<<<DD*DD/1024, 256>>>(Wv, wv_h, wv_l);
    split2k<<<DD*DD/1024, 256>>>(Wo, wo_h, wo_l);
    maskpack_kernel<<<SS*SS/256, 256>>>(mask);

    dim3 gproj(DD / 64, MM / 128);   // (16, 32)

    proj_mma<<<gproj, 256>>>(xa_h, wq_h, wq_l, nullptr, qh_h, nullptr, 1);
    proj_mma<<<gproj, 256>>>(xb_h, wk_h, wk_l, nullptr, kh_h, kh_l,   2);
    proj_mma<<<gproj, 256>>>(xc_h, wv_h, wv_l, nullptr, vt_h, vt_l,   3);

    scores_softmax<<<dim3(SS/16, BH), 256, SC_SMEM>>>(qh_h, kh_h, kh_l, attn, p16);

    ctx_mma<<<dim3(SS/128, BH), 256, CTX_SMEM>>>(p16, vt_h, vt_l, cx_h);

    proj_mma<<<gproj, 256>>>(cx_h, wo_h, wo_l, out, nullptr, nullptr, 0);
}

// round 12
// speedup vs baseline: 4.5344x; 1.0888x over previous
#include <cuda_runtime.h>
#include <cuda_fp16.h>
#include <math.h>

// Problem constants
#define BB   2
#define SS   2048
#define DD   1024
#define HH   16
#define DH   64
#define MM   (BB*SS)     // 4096
#define BH   (BB*HH)     // 32

typedef __half h16;
typedef unsigned uns;

// ---------------------------------------------------------------------------
// Scratch arena (device globals: allocation-free)
// chunks of 4M halves: 0:xa 1:xb 2:xc (act hi), 3:qh, 4:kh_h 5:kh_l,
// 6:vt_h (V transposed hi only), 8:cx_h. weights at 9*CHK: 4x(hi,lo) pairs.
// ---------------------------------------------------------------------------
#define CHK (1u<<22)
#define WCH (1u<<20)
__device__ h16 g_hf[(size_t)9*CHK + 8*WCH];
__device__ h16 g_p16[(size_t)BH*SS*SS];          // fp16 probabilities
__device__ unsigned g_mbits[(size_t)SS*SS/32];

// ---------------------------------------------------------------------------
// helpers
// ---------------------------------------------------------------------------
__device__ __forceinline__ unsigned smem_u32(const void* p){
    unsigned r;
    asm("{ .reg .u64 t; cvta.to.shared.u64 t, %1; cvt.u32.u64 %0, t; }"
        : "=r"(r) : "l"(p));
    return r;
}
#define CP16(dst,src) asm volatile("cp.async.cg.shared.global [%0], [%1], 16;\n" :: "r"(dst), "l"(src))
#define CPCOMMIT()    asm volatile("cp.async.commit_group;\n")
#define CPWAIT(N)     asm volatile("cp.async.wait_group %0;\n" :: "n"(N))

__device__ __forceinline__ uns pkf(float a, float b){
    __half2 t = __floats2half2_rn(a, b);
    return *(uns*)&t;
}
__device__ __forceinline__ uns pkh(h16 a, h16 b){
    return (uns)__half_as_ushort(a) | ((uns)__half_as_ushort(b) << 16);
}
__device__ __forceinline__ void hsplit(float x, h16 &h, h16 &l){
    h = __float2half_rn(x);
    l = __float2half_rn(x - __half2float(h));
}

__device__ __forceinline__ void mma_f16(float c[4], const uns a[4], const uns b0, const uns b1){
    asm volatile("mma.sync.aligned.m16n8k16.row.col.f32.f16.f16.f32 "
        "{%0,%1,%2,%3}, {%4,%5,%6,%7}, {%8,%9}, {%0,%1,%2,%3};"
        : "+f"(c[0]),"+f"(c[1]),"+f"(c[2]),"+f"(c[3])
        : "r"(a[0]),"r"(a[1]),"r"(a[2]),"r"(a[3]),"r"(b0),"r"(b1));
}
__device__ __forceinline__ void ldm4(uns r[4], uns addr){
    asm volatile("ldmatrix.sync.aligned.m8n8.x4.shared.b16 {%0,%1,%2,%3}, [%4];"
        : "=r"(r[0]),"=r"(r[1]),"=r"(r[2]),"=r"(r[3]) : "r"(addr));
}
#define AROW(lane) (((lane)&7) + (((lane)>>3)&1)*8)
#define ACOL(lane) (((lane)>>4)*8)
#define BROW(lane) (((lane)&7) + (((lane)>>4)&1)*8)
#define BCOL(lane) ((((lane)>>3)&1)*8)

// ---------------------------------------------------------------------------
// fused fp32 -> fp16 split kernels
// ---------------------------------------------------------------------------
__global__ __launch_bounds__(256) void split_act(
    const float* __restrict__ q, const float* __restrict__ k,
    const float* __restrict__ v, h16* __restrict__ base)
{
    const float* x = (blockIdx.y == 0) ? q : (blockIdx.y == 1) ? k : v;
    h16* hi = base + (size_t)blockIdx.y * CHK;
    int i = (blockIdx.x * 256 + threadIdx.x) * 4;
    float4 w = *(const float4*)(x + i);
    *(uint2*)(hi + i) = make_uint2(pkf(w.x, w.y), pkf(w.z, w.w));
}
__global__ __launch_bounds__(256) void split_w(
    const float* __restrict__ w0, const float* __restrict__ w1,
    const float* __restrict__ w2, const float* __restrict__ w3,
    h16* __restrict__ base)
{
    const float* x = (blockIdx.y == 0) ? w0 : (blockIdx.y == 1) ? w1
                   : (blockIdx.y == 2) ? w2 : w3;
    h16* hi = base + (size_t)(2*blockIdx.y    ) * WCH;
    h16* lo = base + (size_t)(2*blockIdx.y + 1) * WCH;
    int i = (blockIdx.x * 256 + threadIdx.x) * 4;
    float4 v = *(const float4*)(x + i);
    h16 h0,l0,h1,l1,h2,l2,h3,l3;
    hsplit(v.x,h0,l0); hsplit(v.y,h1,l1); hsplit(v.z,h2,l2); hsplit(v.w,h3,l3);
    *(uint2*)(hi + i) = make_uint2(pkh(h0,h1), pkh(h2,h3));
    *(uint2*)(lo + i) = make_uint2(pkh(l0,l1), pkh(l2,l3));
}

__global__ __launch_bounds__(256) void maskpack_kernel(const int* __restrict__ mask)
{
    int i = blockIdx.x * 256 + threadIdx.x;
    unsigned w = __ballot_sync(0xffffffffu, mask[i] != 0);
    if ((threadIdx.x & 31) == 0) g_mbits[i >> 5] = w;
}

// ---------------------------------------------------------------------------
// C = A[M,K] @ W[N,K]^T, fp16. comp=1: one-sided W compensation (2 MMA/k16);
// comp=0: plain fp16 (1 MMA/k16). ldmatrix frag loads.
// CTA 128(M) x 64(N), k-tile 32, 256 thr = 8 warps (4m x 2n), warp 32x32.
// mode 0: fp32 flat  1: hi-only [BH,S,DH]  2: hi+lo [BH,S,DH]  3: hi T [BH,DH,S]
// ---------------------------------------------------------------------------
__global__ __launch_bounds__(256) void proj_mma(
    const h16* __restrict__ Ah_g,
    const h16* __restrict__ Wh_g, const h16* __restrict__ Wl_g,
    float* __restrict__ Cf, h16* __restrict__ Ch, h16* __restrict__ Cl,
    int mode, int comp)
{
    __shared__ h16 As[2][128][40];
    __shared__ h16 Ws[2][2][64][40];   // [pl][stage]

    const int tid = threadIdx.x, lane = tid & 31, wid = tid >> 5;
    const int wm = wid >> 1, wn = wid & 1;
    const int g = lane >> 2, t = lane & 3;
    const int m0 = blockIdx.y * 128, n0 = blockIdx.x * 64;

    const uns as_a = smem_u32(&As[0][0][0]);
    const uns ws_a = smem_u32(&Ws[0][0][0][0]);
    const int arow = AROW(lane), acol = ACOL(lane);
    const int brow = BROW(lane), bcol = BCOL(lane);

    float acc[2][4][4];
    #pragma unroll
    for (int i=0;i<2;i++)
        #pragma unroll
        for (int j=0;j<4;j++)
            #pragma unroll
            for (int e=0;e<4;e++) acc[i][j][e]=0.f;

    auto pre = [&](int kt, int s){
        const int k0 = kt * 32;
        #pragma unroll
        for (int i = 0; i < 2; i++){               // A: 512 chunks
            int idx = tid + i*256;
            int r = idx >> 2, c = idx & 3;
            CP16(smem_u32(&As[s][r][c*8]), Ah_g + (size_t)(m0+r)*DD + k0 + c*8);
        }
        if (comp){
            #pragma unroll
            for (int i = 0; i < 2; i++){           // W: 512 chunks (2 planes)
                int idx = tid + i*256;
                int pl = idx >> 8, rem = idx & 255;
                int r = rem >> 2, c = rem & 3;
                CP16(smem_u32(&Ws[pl][s][r][c*8]),
                     (pl ? Wl_g : Wh_g) + (size_t)(n0+r)*DD + k0 + c*8);
            }
        } else {
            {                                       // W hi only: 256 chunks
                int r = tid >> 2, c = tid & 3;
                CP16(smem_u32(&Ws[0][s][r][c*8]),
                     Wh_g + (size_t)(n0+r)*DD + k0 + c*8);
            }
        }
        CPCOMMIT();
    };

    pre(0, 0);
    const int NT = DD / 32;   // 32
    for (int kt = 0; kt < NT; kt++){
        const int s = kt & 1;
        if (kt + 1 < NT){ pre(kt + 1, s ^ 1); CPWAIT(1); }
        else            { CPWAIT(0); }
        __syncthreads();

        #pragma unroll
        for (int ks = 0; ks < 2; ks++){
            const int k0 = ks*16;
            uns ah[2][4];
            #pragma unroll
            for (int mt = 0; mt < 2; mt++)
                ldm4(ah[mt], as_a + ((s*128 + wm*32 + mt*16 + arow)*40
                                     + k0 + acol)*2);
            uns bhq[2][4], blq[2][4];
            #pragma unroll
            for (int hq = 0; hq < 2; hq++){
                ldm4(bhq[hq], ws_a + (((0*2+s)*64 + wn*32 + hq*16 + brow)*40
                                      + k0 + bcol)*2);
                if (comp)
                    ldm4(blq[hq], ws_a + (((1*2+s)*64 + wn*32 + hq*16 + brow)*40
                                          + k0 + bcol)*2);
            }
            #pragma unroll
            for (int mt = 0; mt < 2; mt++)
                #pragma unroll
                for (int nt = 0; nt < 4; nt++){
                    const int hq = nt >> 1, p = (nt & 1) * 2;
                    mma_f16(acc[mt][nt], ah[mt], bhq[hq][p], bhq[hq][p+1]);
                    if (comp)
                        mma_f16(acc[mt][nt], ah[mt], blq[hq][p], blq[hq][p+1]);
                }
        }
        __syncthreads();
    }

    #pragma unroll
    for (int mt = 0; mt < 2; mt++){
        #pragma unroll
        for (int nt = 0; nt < 4; nt++){
            const int r0 = m0 + wm*32 + mt*16 + g;
            const int r1 = r0 + 8;
            const int cb = n0 + wn*32 + nt*8 + 2*t;
            float* a = acc[mt][nt];
            if (mode == 0){
                *(float2*)&Cf[(size_t)r0*DD + cb] = make_float2(a[0], a[1]);
                *(float2*)&Cf[(size_t)r1*DD + cb] = make_float2(a[2], a[3]);
            } else if (mode == 1 || mode == 2){
                const int h = cb >> 6, dh = cb & 63;
                #pragma unroll
                for (int p = 0; p < 2; p++){
                    int m = p ? r1 : r0;
                    int b = m >> 11, sq = m & (SS - 1);
                    size_t base = (((size_t)(b*HH + h))*SS + sq)*DH + dh;
                    float x0 = a[p*2], x1 = a[p*2+1];
                    if (mode == 1){
                        *(uns*)&Ch[base] = pkf(x0, x1);
                    } else {
                        h16 h0,l0,h1,l1;
                        hsplit(x0,h0,l0); hsplit(x1,h1,l1);
                        *(uns*)&Ch[base] = pkh(h0,h1);
                        *(uns*)&Cl[base] = pkh(l0,l1);
                    }
                }
            } else {   // mode 3: hi-only transposed [BH,DH,S]
                #pragma unroll
                for (int e = 0; e < 4; e++){
                    int m = (e < 2) ? r0 : r1;
                    int n = cb + (e & 1);
                    int b = m >> 11, sq = m & (SS - 1);
                    int h = n >> 6, dh = n & 63;
                    size_t idx = (((size_t)(b*HH + h))*DH + dh)*SS + sq;
                    Ch[idx] = __float2half_rn(a[e]);
                }
            }
        }
    }
}

// ---------------------------------------------------------------------------
// Fused scores + mask + softmax. Mask+row-max folded into MMA epilogue.
// Emits attn (fp32, output) and p16 (fp16 copy for ctx).
// ---------------------------------------------------------------------------
#define SC_SMEM (16*2052*4 + 16*72*2 + 2*2*128*72*2 + 64 + 512)

__global__ __launch_bounds__(256) void scores_softmax(
    const h16* __restrict__ Qh_g,
    const h16* __restrict__ Kh_g, const h16* __restrict__ Kl_g,
    float* __restrict__ attn, h16* __restrict__ p16)
{
    extern __shared__ __align__(16) unsigned char dynsm[];
    float* ps  = (float*)dynsm;
    h16* qsm   = (h16*)(dynsm + 16*2052*4);
    h16* ksm   = (h16*)(dynsm + 16*2052*4 + 16*72*2);
    float* invs= (float*)(dynsm + 16*2052*4 + 16*72*2 + 2*2*128*72*2);
    float* wmax= invs + 16;                       // [16][8]

    const int tid = threadIdx.x, lane = tid & 31, wid = tid >> 5;
    const int g = lane >> 2, t = lane & 3;
    const int bh = blockIdx.y, q0 = blockIdx.x * 16;

    const uns q_a = smem_u32(qsm);
    const uns k_a = smem_u32(ksm);
    const int arow = AROW(lane), acol = ACOL(lane);
    const int brow = BROW(lane), bcol = BCOL(lane);

    if (tid < 128){
        int r = tid >> 3, c = tid & 7;
        CP16(smem_u32(qsm + r*72 + c*8),
             Qh_g + ((size_t)bh*SS + q0 + r)*DH + c*8);
    }

    auto pre = [&](int kb, int s){
        #pragma unroll
        for (int i = 0; i < 8; i++){
            int idx = tid + i*256;
            int pl = idx >> 10, j = idx & 1023;
            int r = j >> 3, c = j & 7;
            const h16* src = (pl ? Kl_g : Kh_g)
                           + ((size_t)bh*SS + kb*128 + r)*DH + c*8;
            CP16(smem_u32(ksm + ((s*2+pl)*128 + r)*72 + c*8), src);
        }
        CPCOMMIT();
    };

    pre(0, 0);

    uns qa[4][4];
    const int nbase = wid * 16;
    float mr0 = -3.0e38f, mr8 = -3.0e38f;

    for (int kb = 0; kb < 16; kb++){
        const int s = kb & 1;
        if (kb + 1 < 16){ pre(kb + 1, s ^ 1); CPWAIT(1); }
        else            { CPWAIT(0); }
        __syncthreads();

        if (kb == 0){
            #pragma unroll
            for (int ck = 0; ck < 4; ck++)
                ldm4(qa[ck], q_a + (arow*72 + ck*16 + acol)*2);
        }

        float acc[2][4] = {{0.f,0.f,0.f,0.f},{0.f,0.f,0.f,0.f}};
        #pragma unroll
        for (int ck = 0; ck < 4; ck++){
            uns bh2[4], bl2[4];
            ldm4(bh2, k_a + (((s*2+0)*128 + nbase + brow)*72 + ck*16 + bcol)*2);
            ldm4(bl2, k_a + (((s*2+1)*128 + nbase + brow)*72 + ck*16 + bcol)*2);
            mma_f16(acc[0], qa[ck], bh2[0], bh2[1]);
            mma_f16(acc[0], qa[ck], bl2[0], bl2[1]);
            mma_f16(acc[1], qa[ck], bh2[2], bh2[3]);
            mma_f16(acc[1], qa[ck], bl2[2], bl2[3]);
        }

        #pragma unroll
        for (int nt = 0; nt < 2; nt++){
            const int col = kb*128 + nbase + nt*8 + 2*t;
            const unsigned w0 = g_mbits[((size_t)(q0 + g    )*SS + col) >> 5];
            const unsigned w8 = g_mbits[((size_t)(q0 + g + 8)*SS + col) >> 5];
            const int sh = col & 31;
            float s0 = ((w0 >> sh)     & 1) ? acc[nt][0]*0.125f : -1e34f;
            float s1 = ((w0 >> (sh+1)) & 1) ? acc[nt][1]*0.125f : -1e34f;
            float s2 = ((w8 >> sh)     & 1) ? acc[nt][2]*0.125f : -1e34f;
            float s3 = ((w8 >> (sh+1)) & 1) ? acc[nt][3]*0.125f : -1e34f;
            ps[(g    )*2052 + col    ] = s0;
            ps[(g    )*2052 + col + 1] = s1;
            ps[(g + 8)*2052 + col    ] = s2;
            ps[(g + 8)*2052 + col + 1] = s3;
            mr0 = fmaxf(mr0, fmaxf(s0, s1));
            mr8 = fmaxf(mr8, fmaxf(s2, s3));
        }
        __syncthreads();
    }

    #pragma unroll
    for (int off = 1; off < 4; off <<= 1){
        mr0 = fmaxf(mr0, __shfl_xor_sync(0xffffffffu, mr0, off));
        mr8 = fmaxf(mr8, __shfl_xor_sync(0xffffffffu, mr8, off));
    }
    if (t == 0){
        wmax[(g    )*8 + wid] = mr0;
        wmax[(g + 8)*8 + wid] = mr8;
    }
    __syncthreads();

    const int row = tid >> 4, sub = tid & 15;
    float* pr = ps + row * 2052;

    float mx = -3.0e38f;
    #pragma unroll
    for (int j = 0; j < 8; j++) mx = fmaxf(mx, wmax[row*8 + j]);

    float sum = 0.f;
    for (int k2 = sub; k2 < SS; k2 += 16){
        float e = __expf(pr[k2] - mx);
        pr[k2] = e;
        sum += e;
    }
    #pragma unroll
    for (int off = 1; off < 16; off <<= 1)
        sum += __shfl_xor_sync(0xffffffffu, sum, off);

    if (sub == 0) invs[row] = 1.f / sum;
    __syncthreads();

    float* Ar = attn + ((size_t)bh * SS + q0) * SS;
    h16*   Pr = p16  + ((size_t)bh * SS + q0) * SS;
    #pragma unroll
    for (int i = 0; i < 32; i++){
        int idx = tid + i * 256;
        int r = idx >> 9, c4 = idx & 511;
        float inv = invs[r];
        float4 v = *(float4*)&ps[r * 2052 + c4 * 4];
        v.x *= inv; v.y *= inv; v.z *= inv; v.w *= inv;
        *(float4*)&Ar[(size_t)r * SS + c4 * 4] = v;
        *(uint2*)&Pr[(size_t)r * SS + c4 * 4] = make_uint2(pkf(v.x, v.y),
                                                           pkf(v.z, v.w));
    }
}

// ---------------------------------------------------------------------------
// ctx = P16 @ V (plain fp16: V hi only). ldmatrix frags, k-tile 64 keys.
// dyn smem: Ps[2][128][72]h + Vs[2][64][72]h = 55296 B
// ---------------------------------------------------------------------------
#define CTX_SMEM (2*128*72*2 + 2*64*72*2)

__global__ __launch_bounds__(256) void ctx_mma(
    const h16* __restrict__ P16,
    const h16* __restrict__ Vh_g,
    h16* __restrict__ Ch)
{
    extern __shared__ __align__(16) unsigned char dynsm[];
    h16* Psm = (h16*)dynsm;                    // [2][128][72]
    h16* Vsm = (h16*)(dynsm + 2*128*72*2);     // [2][64][72]

    const int tid = threadIdx.x, lane = tid & 31, wid = tid >> 5;
    const int wm = wid >> 1, wn = wid & 1;
    const int g = lane >> 2, t = lane & 3;
    const int bh = blockIdx.y, q0 = blockIdx.x * 128;

    const uns p_a = smem_u32(Psm);
    const uns v_a = smem_u32(Vsm);
    const int arow = AROW(lane), acol = ACOL(lane);
    const int brow = BROW(lane), bcol = BCOL(lane);

    const h16* Pb  = P16  + (size_t)bh * SS * SS;
    const h16* Vhb = Vh_g + (size_t)bh * DH * SS;

    float acc[2][4][4];
    #pragma unroll
    for (int i=0;i<2;i++)
        #pragma unroll
        for (int j=0;j<4;j++)
            #pragma unroll
            for (int e=0;e<4;e++) acc[i][j][e]=0.f;

    auto pre = [&](int kt, int s){
        const int k0 = kt * 64;
        #pragma unroll
        for (int i = 0; i < 4; i++){           // P: 1024 chunks (128r x 8c)
            int idx = tid + i*256;
            int r = idx >> 3, c = idx & 7;
            CP16(smem_u32(Psm + (s*128 + r)*72 + c*8),
                 Pb + (size_t)(q0 + r)*SS + k0 + c*8);
        }
        #pragma unroll
        for (int i = 0; i < 2; i++){           // V: 512 chunks (64r x 8c)
            int idx = tid + i*256;
            int r = idx >> 3, c = idx & 7;
            CP16(smem_u32(Vsm + (s*64 + r)*72 + c*8),
                 Vhb + (size_t)r*SS + k0 + c*8);
        }
        CPCOMMIT();
    };

    pre(0, 0);
    const int NT = SS / 64;   // 32
    for (int kt = 0; kt < NT; kt++){
        const int s = kt & 1;
        if (kt + 1 < NT){ pre(kt + 1, s ^ 1); CPWAIT(1); }
        else            { CPWAIT(0); }
        __syncthreads();

        #pragma unroll
        for (int ks = 0; ks < 4; ks++){
            const int k0 = ks*16;
            uns ah[2][4];
            #pragma unroll
            for (int mt = 0; mt < 2; mt++)
                ldm4(ah[mt], p_a + ((s*128 + wm*32 + mt*16 + arow)*72
                                    + k0 + acol)*2);
            uns bhq[2][4];
            #pragma unroll
            for (int hq = 0; hq < 2; hq++)
                ldm4(bhq[hq], v_a + ((s*64 + wn*32 + hq*16 + brow)*72
                                     + k0 + bcol)*2);
            #pragma unroll
            for (int mt = 0; mt < 2; mt++)
                #pragma unroll
                for (int nt = 0; nt < 4; nt++){
                    const int hq = nt >> 1, p = (nt & 1) * 2;
                    mma_f16(acc[mt][nt], ah[mt], bhq[hq][p], bhq[hq][p+1]);
                }
        }
        __syncthreads();
    }

    const int b = bh >> 4, h = bh & 15;
    #pragma unroll
    for (int mt = 0; mt < 2; mt++){
        #pragma unroll
        for (int nt = 0; nt < 4; nt++){
            const int r0 = q0 + wm*32 + mt*16 + g;
            const int r1 = r0 + 8;
            const int cb = h*64 + wn*32 + nt*8 + 2*t;
            float* a = acc[mt][nt];
            *(uns*)&Ch[(size_t)(b*SS + r0)*DD + cb] = pkf(a[0], a[1]);
            *(uns*)&Ch[(size_t)(b*SS + r1)*DD + cb] = pkf(a[2], a[3]);
        }
    }
}

// ---------------------------------------------------------------------------
extern "C" void kernel_launch(void* const* d_in, const int* in_sizes, int n_in,
                              void* d_out, int out_size)
{
    const float* q    = (const float*)d_in[0];
    const float* k    = (const float*)d_in[1];
    const float* v    = (const float*)d_in[2];
    const int*   mask = (const int*)  d_in[3];
    const float* Wq   = (const float*)d_in[4];
    const float* Wk   = (const float*)d_in[5];
    const float* Wv   = (const float*)d_in[6];
    const float* Wo   = (const float*)d_in[7];

    float* out  = (float*)d_out;               // [B,S,D]
    float* attn = out + (size_t)MM * DD;       // [B,H,S,S]

    h16* P; cudaGetSymbolAddress((void**)&P, g_hf);
    h16* p16; cudaGetSymbolAddress((void**)&p16, g_p16);
    h16 *xa_h = P + (size_t)0*CHK;
    h16 *xb_h = P + (size_t)1*CHK;
    h16 *xc_h = P + (size_t)2*CHK;
    h16 *qh_h = P + (size_t)3*CHK;
    h16 *kh_h = P + (size_t)4*CHK, *kh_l = P + (size_t)5*CHK;
    h16 *vt_h = P + (size_t)6*CHK;
    h16 *cx_h = P + (size_t)8*CHK;
    h16 *wb   = P + (size_t)9*CHK;
    h16 *wq_h = wb + (size_t)0*WCH, *wq_l = wb + (size_t)1*WCH;
    h16 *wk_h = wb + (size_t)2*WCH, *wk_l = wb + (size_t)3*WCH;
    h16 *wv_h = wb + (size_t)4*WCH;
    h16 *wo_h = wb + (size_t)6*WCH;

    cudaFuncSetAttribute(scores_softmax,
        cudaFuncAttributeMaxDynamicSharedMemorySize, SC_SMEM);
    cudaFuncSetAttribute(ctx_mma,
        cudaFuncAttributeMaxDynamicSharedMemorySize, CTX_SMEM);

    // launch order chosen so the ncu window (-s 5 -c 1) profiles scores_softmax
    split_act<<<dim3(MM*DD/1024, 3), 256>>>(q, k, v, P);          // 0
    split_w  <<<dim3(DD*DD/1024, 4), 256>>>(Wq, Wk, Wv, Wo, wb);  // 1
    maskpack_kernel<<<SS*SS/256, 256>>>(mask);                    // 2

    dim3 gproj(DD / 64, MM / 128);   // (16, 32)

    proj_mma<<<gproj, 256>>>(xa_h, wq_h, wq_l, nullptr, qh_h, nullptr, 1, 1); // 3
    proj_mma<<<gproj, 256>>>(xb_h, wk_h, wk_l, nullptr, kh_h, kh_l,   2, 1);  // 4

    scores_softmax<<<dim3(SS/16, BH), 256, SC_SMEM>>>(qh_h, kh_h, kh_l,
                                                      attn, p16);             // 5
    proj_mma<<<gproj, 256>>>(xc_h, wv_h, nullptr, nullptr, vt_h, nullptr, 3, 0); // 6

    ctx_mma<<<dim3(SS/128, BH), 256, CTX_SMEM>>>(p16, vt_h, cx_h);            // 7

    proj_mma<<<gproj, 256>>>(cx_h, wo_h, nullptr, out, nullptr, nullptr, 0, 0); // 8
}